// round 5
// baseline (speedup 1.0000x reference)
#include <cuda_runtime.h>
#include <cstdint>
#include <math.h>

#define Bc 8
#define Nc 2048
#define Kc 20
#define EMBc 1024
#define EPSc 1e-5
#define SLOPEc 0.2f

// ---------------- scratch (static device globals; no allocation allowed) ----------------
__device__ double g_distd[(size_t)Bc * Nc * Nc];   // 256 MB pairwise "pd" values (near-exact)
__device__ double g_xxd[Bc * Nc];
__device__ int    g_idx[Bc * Nc * Kc];
__device__ float  g_x1[Bc * 64 * Nc];
__device__ float  g_x2[Bc * 64 * Nc];
__device__ float  g_x3[Bc * 128 * Nc];
__device__ float  g_x4[Bc * 256 * Nc];
__device__ float  g_wT[256 * 256];
__device__ float  g_ymax[Bc * Nc * 256];           // [b][n][o] pre-BN max over k
__device__ double g_statsd[2 * EMBc];              // per-channel sum / sumsq (fp64)
__device__ float  g_z5[Bc * EMBc * Nc];            // 64 MB conv5 pre-BN output
__device__ float  g_p[Bc * 2 * EMBc];
__device__ float  g_h1[Bc * 512];
__device__ float  g_h2[Bc * 256];

// ---------------- kernels ----------------

// xx = sum_c x^2, exact in fp64 (tiny: 16k points x <=256 ch)
__global__ void xx_kernel(const float* __restrict__ x, double* __restrict__ xx, int C)
{
    int i = blockIdx.x * blockDim.x + threadIdx.x;
    if (i >= Bc * Nc) return;
    int b = i / Nc, n = i % Nc;
    double s = 0.0;
    for (int c = 0; c < C; c++) {
        double v = (double)x[((size_t)b * C + c) * Nc + n];
        s += v * v;
    }
    xx[i] = s;
}

// pd[b,n,m] = 2*dot - xx_n - xx_m, dot accumulated as compensated fp32
// (8-term fma chunks + Neumaier merge), combined in fp64 -> near-true ordering.
__global__ void dist_kernel(const float* __restrict__ x, const double* __restrict__ xx,
                            double* __restrict__ dist, int C)
{
    __shared__ float sn[8][32];
    __shared__ float sm_[8][32];
    int b = blockIdx.z;
    int n0 = blockIdx.y * 32, m0 = blockIdx.x * 32;
    int t = threadIdx.x;
    int tx = t & 15, ty = t >> 4;
    float s00 = 0.f, s01 = 0.f, s10 = 0.f, s11 = 0.f;   // compensated sums
    float e00 = 0.f, e01 = 0.f, e10 = 0.f, e11 = 0.f;   // compensation terms
    const float* xb = x + (size_t)b * C * Nc;

    for (int c0 = 0; c0 < C; c0 += 8) {
        int cc = t >> 5, j = t & 31;
        int c = c0 + cc;
        sn[cc][j]  = (c < C) ? xb[(size_t)c * Nc + n0 + j] : 0.f;
        sm_[cc][j] = (c < C) ? xb[(size_t)c * Nc + m0 + j] : 0.f;
        __syncthreads();
        float a00 = 0.f, a01 = 0.f, a10 = 0.f, a11 = 0.f;
#pragma unroll
        for (int q = 0; q < 8; q++) {
            float n0v = sn[q][ty * 2], n1v = sn[q][ty * 2 + 1];
            float m0v = sm_[q][tx * 2], m1v = sm_[q][tx * 2 + 1];
            a00 = fmaf(n0v, m0v, a00); a01 = fmaf(n0v, m1v, a01);
            a10 = fmaf(n1v, m0v, a10); a11 = fmaf(n1v, m1v, a11);
        }
        // Neumaier merge of chunk a into (s, e)
        {
            float tt;
            tt = s00 + a00; e00 += (fabsf(s00) >= fabsf(a00)) ? ((s00 - tt) + a00) : ((a00 - tt) + s00); s00 = tt;
            tt = s01 + a01; e01 += (fabsf(s01) >= fabsf(a01)) ? ((s01 - tt) + a01) : ((a01 - tt) + s01); s01 = tt;
            tt = s10 + a10; e10 += (fabsf(s10) >= fabsf(a10)) ? ((s10 - tt) + a10) : ((a10 - tt) + s10); s10 = tt;
            tt = s11 + a11; e11 += (fabsf(s11) >= fabsf(a11)) ? ((s11 - tt) + a11) : ((a11 - tt) + s11); s11 = tt;
        }
        __syncthreads();
    }
    int n = n0 + ty * 2, m = m0 + tx * 2;
    double xn0 = xx[b * Nc + n], xn1 = xx[b * Nc + n + 1];
    double xm0 = xx[b * Nc + m], xm1 = xx[b * Nc + m + 1];
    double d00 = (double)s00 + (double)e00;
    double d01 = (double)s01 + (double)e01;
    double d10 = (double)s10 + (double)e10;
    double d11 = (double)s11 + (double)e11;
    double* dr = dist + (size_t)b * Nc * Nc;
    dr[(size_t)n * Nc + m]           = 2.0 * d00 - xn0 - xm0;
    dr[(size_t)n * Nc + m + 1]       = 2.0 * d01 - xn0 - xm1;
    dr[(size_t)(n + 1) * Nc + m]     = 2.0 * d10 - xn1 - xm0;
    dr[(size_t)(n + 1) * Nc + m + 1] = 2.0 * d11 - xn1 - xm1;
}

// one warp per row: 20 iterative argmax passes over fp64 pd, ties -> lowest index
__global__ void topk_kernel(const double* __restrict__ dist, int* __restrict__ idx)
{
    __shared__ double sv[Nc];
    int row = blockIdx.x;                 // b*Nc + n
    int lane = threadIdx.x;
    const double* d = dist + (size_t)row * Nc;
    for (int j = lane; j < Nc; j += 32) sv[j] = d[j];
    __syncwarp();
    for (int kk = 0; kk < Kc; kk++) {
        double bv = -INFINITY; int bi = Nc;
        for (int j = lane; j < Nc; j += 32) {
            double v = sv[j];
            if (v > bv) { bv = v; bi = j; }   // ascending j -> lowest idx kept on ties
        }
        for (int off = 16; off; off >>= 1) {
            double ov = __shfl_xor_sync(0xffffffffu, bv, off);
            int    oi = __shfl_xor_sync(0xffffffffu, bi, off);
            if (ov > bv || (ov == bv && oi < bi)) { bv = ov; bi = oi; }
        }
        if (lane == 0) { idx[(size_t)row * Kc + kk] = bi; sv[bi] = -INFINITY; }
        __syncwarp();
    }
}

__global__ void transpose_kernel(const float* __restrict__ w, float* __restrict__ wT,
                                 int O, int C2)
{
    int t = blockIdx.x * blockDim.x + threadIdx.x;
    if (t < O * C2) { int o = t / C2, c = t % C2; wT[c * O + o] = w[t]; }
}

// fused: gather graph feature -> 1x1 conv -> fp64 per-channel sum/sumsq -> max over k (pre-BN)
__global__ void edgeconv_kernel(const float* __restrict__ xin, const float* __restrict__ wT,
                                const int* __restrict__ idx, float* __restrict__ ymax,
                                double* __restrict__ stats, int C, int O)
{
    extern __shared__ float shm[];
    int n = blockIdx.x, b = blockIdx.y, t = threadIdx.x;
    int C2 = 2 * C;
    float* feat = shm;                // [C2][Kc]
    float* ctr  = shm + C2 * Kc;      // [C]
    int*   sidx = (int*)(ctr + C);    // [Kc]

    if (t < Kc) sidx[t] = idx[((size_t)b * Nc + n) * Kc + t];
    for (int c = t; c < C; c += blockDim.x)
        ctr[c] = xin[((size_t)b * C + c) * Nc + n];
    __syncthreads();
    for (int e = t; e < C * Kc; e += blockDim.x) {
        int c = e / Kc, k = e - c * Kc;
        float cv = ctr[c];
        float nv = xin[((size_t)b * C + c) * Nc + sidx[k]];
        feat[c * Kc + k]       = __fsub_rn(nv, cv);  // channels [0,C): nbr - ctr
        feat[(C + c) * Kc + k] = cv;                 // channels [C,2C): ctr
    }
    __syncthreads();

    float acc[Kc];
#pragma unroll
    for (int k = 0; k < Kc; k++) acc[k] = 0.f;

#pragma unroll 2
    for (int c2 = 0; c2 < C2; c2++) {
        float w = wT[c2 * O + t];
        const float4* fr = reinterpret_cast<const float4*>(feat + c2 * Kc);
#pragma unroll
        for (int q = 0; q < Kc / 4; q++) {
            float4 f = fr[q];
            acc[4 * q + 0] = fmaf(w, f.x, acc[4 * q + 0]);
            acc[4 * q + 1] = fmaf(w, f.y, acc[4 * q + 1]);
            acc[4 * q + 2] = fmaf(w, f.z, acc[4 * q + 2]);
            acc[4 * q + 3] = fmaf(w, f.w, acc[4 * q + 3]);
        }
    }

    float m = acc[0];
    double s = 0.0, ss = 0.0;
#pragma unroll
    for (int k = 0; k < Kc; k++) {
        m = fmaxf(m, acc[k]);
        double a = (double)acc[k];
        s += a;
        ss += a * a;
    }
    ymax[((size_t)b * Nc + n) * O + t] = m;   // coalesced across o
    atomicAdd(&stats[t], s);
    atomicAdd(&stats[O + t], ss);
}

// BN + lrelu on the max-pooled values (monotone transform commutes with max)
__global__ void bnapply_kernel(const float* __restrict__ ymax, const double* __restrict__ stats,
                               const float* __restrict__ g, const float* __restrict__ bta,
                               float* __restrict__ xout, int O, double invcnt)
{
    int i = blockIdx.x * blockDim.x + threadIdx.x;
    if (i >= Bc * Nc * O) return;
    int o = i % O;
    int n = (i / O) % Nc;
    int b = i / (O * Nc);
    double mean = stats[o] * invcnt;
    double var  = stats[O + o] * invcnt - mean * mean;
    float m = (float)mean;
    float r = (float)rsqrt(var + EPSc);
    float v = __fadd_rn(__fmul_rn(__fmul_rn(__fsub_rn(ymax[i], m), r), g[o]), bta[o]);
    xout[((size_t)b * O + o) * Nc + n] = (v >= 0.f) ? v : SLOPEc * v;
}

// conv5: z[b,o,n] = sum_c w5[o,c]*cat[b,c,n]; cat channels map to x1/x2/x3/x4.
__global__ void conv5_kernel(const float* __restrict__ w5,
                             const float* __restrict__ x1, const float* __restrict__ x2,
                             const float* __restrict__ x3, const float* __restrict__ x4,
                             float* __restrict__ z, double* __restrict__ stats)
{
    __shared__ float As[16][65];
    __shared__ float Bs[16][64];
    __shared__ double rs[64], rss[64];
    int b  = blockIdx.z;
    int o0 = blockIdx.y * 64;
    int n0 = blockIdx.x * 64;
    int t = threadIdx.x;
    int tx = t & 15, ty = t >> 4;
    float acc[4][4];
#pragma unroll
    for (int i = 0; i < 4; i++)
#pragma unroll
        for (int j = 0; j < 4; j++) acc[i][j] = 0.f;

    for (int c0 = 0; c0 < 512; c0 += 16) {
#pragma unroll
        for (int r = 0; r < 4; r++) {
            int e = t + r * 256;
            int oo = e >> 4, cc = e & 15;
            As[cc][oo] = w5[(size_t)(o0 + oo) * 512 + c0 + cc];
            int cc2 = e >> 6, jj = e & 63;
            int ch = c0 + cc2;
            const float* src; int cl, Cb;
            if (ch < 64)       { src = x1; cl = ch;       Cb = 64;  }
            else if (ch < 128) { src = x2; cl = ch - 64;  Cb = 64;  }
            else if (ch < 256) { src = x3; cl = ch - 128; Cb = 128; }
            else               { src = x4; cl = ch - 256; Cb = 256; }
            Bs[cc2][jj] = src[((size_t)b * Cb + cl) * Nc + n0 + jj];
        }
        __syncthreads();
#pragma unroll
        for (int cc = 0; cc < 16; cc++) {
            float av[4], bv[4];
#pragma unroll
            for (int i = 0; i < 4; i++) av[i] = As[cc][ty * 4 + i];
#pragma unroll
            for (int j = 0; j < 4; j++) bv[j] = Bs[cc][tx * 4 + j];
#pragma unroll
            for (int i = 0; i < 4; i++)
#pragma unroll
                for (int j = 0; j < 4; j++)
                    acc[i][j] = fmaf(av[i], bv[j], acc[i][j]);
        }
        __syncthreads();
    }
    if (t < 64) { rs[t] = 0.0; rss[t] = 0.0; }
    __syncthreads();
#pragma unroll
    for (int i = 0; i < 4; i++) {
        int o = o0 + ty * 4 + i;
        double s = 0.0, ss = 0.0;
#pragma unroll
        for (int j = 0; j < 4; j++) { double v = (double)acc[i][j]; s += v; ss += v * v; }
        atomicAdd(&rs[ty * 4 + i], s);
        atomicAdd(&rss[ty * 4 + i], ss);
        float4 v4 = make_float4(acc[i][0], acc[i][1], acc[i][2], acc[i][3]);
        *reinterpret_cast<float4*>(&z[((size_t)b * EMBc + o) * Nc + n0 + tx * 4]) = v4;
    }
    __syncthreads();
    if (t < 64) {
        atomicAdd(&stats[o0 + t], rs[t]);
        atomicAdd(&stats[EMBc + o0 + t], rss[t]);
    }
}

// BN + lrelu + max/mean pooling over n for one (b, o) per warp
__global__ void pool5_kernel(const float* __restrict__ z, const double* __restrict__ stats,
                             const float* __restrict__ g, const float* __restrict__ bta,
                             float* __restrict__ p)
{
    int o = blockIdx.x, b = blockIdx.y, lane = threadIdx.x;
    const double inv = 1.0 / (double)(Bc * Nc);
    double mean = stats[o] * inv;
    double var  = stats[EMBc + o] * inv - mean * mean;
    float m = (float)mean;
    float r = (float)rsqrt(var + EPSc);
    float gg = g[o], bb = bta[o];
    const float* row = z + ((size_t)b * EMBc + o) * Nc;
    float mx = -INFINITY, sm = 0.f;
    for (int j = lane; j < Nc; j += 32) {
        float v = __fadd_rn(__fmul_rn(__fmul_rn(__fsub_rn(row[j], m), r), gg), bb);
        v = (v >= 0.f) ? v : SLOPEc * v;
        mx = fmaxf(mx, v);
        sm += v;
    }
    for (int off = 16; off; off >>= 1) {
        mx = fmaxf(mx, __shfl_xor_sync(0xffffffffu, mx, off));
        sm += __shfl_xor_sync(0xffffffffu, sm, off);
    }
    if (lane == 0) {
        p[b * 2 * EMBc + o] = mx;
        p[b * 2 * EMBc + EMBc + o] = sm * (1.0f / Nc);
    }
}

// fully-connected + batch BN (over B=8, fp64 moments) + lrelu; one output feature per block
__global__ void fc_bn_kernel(const float* __restrict__ in, const float* __restrict__ W,
                             const float* __restrict__ bias, const float* __restrict__ g,
                             const float* __restrict__ bta, float* __restrict__ out,
                             int Cin, int Cout)
{
    int j = blockIdx.x, t = threadIdx.x;
    float a[Bc];
#pragma unroll
    for (int b_ = 0; b_ < Bc; b_++) a[b_] = 0.f;
    for (int e = t; e < Cin; e += 64) {
        float w = W[(size_t)j * Cin + e];
#pragma unroll
        for (int b_ = 0; b_ < Bc; b_++) a[b_] = fmaf(w, in[b_ * Cin + e], a[b_]);
    }
    __shared__ float red[64][Bc];
#pragma unroll
    for (int b_ = 0; b_ < Bc; b_++) red[t][b_] = a[b_];
    __syncthreads();
    for (int s = 32; s > 0; s >>= 1) {
        if (t < s) {
#pragma unroll
            for (int b_ = 0; b_ < Bc; b_++) red[t][b_] += red[t + s][b_];
        }
        __syncthreads();
    }
    if (t < Bc) {
        float bb = bias ? bias[j] : 0.f;
        float vals[Bc];
        double mean = 0.0;
#pragma unroll
        for (int b_ = 0; b_ < Bc; b_++) { vals[b_] = red[0][b_] + bb; mean += (double)vals[b_]; }
        mean *= (1.0 / Bc);
        double var = 0.0;
#pragma unroll
        for (int b_ = 0; b_ < Bc; b_++) { double d = (double)vals[b_] - mean; var += d * d; }
        var *= (1.0 / Bc);
        float m = (float)mean;
        float r = (float)rsqrt(var + EPSc);
        float y = __fadd_rn(__fmul_rn(__fmul_rn(__fsub_rn(vals[t], m), r), g[j]), bta[j]);
        out[t * Cout + j] = (y >= 0.f) ? y : SLOPEc * y;
    }
}

__global__ void fc3_kernel(const float* __restrict__ in, const float* __restrict__ W,
                           const float* __restrict__ bias, float* __restrict__ out)
{
    int t = threadIdx.x;
    if (t >= Bc * 40) return;
    int b = t / 40, j = t % 40;
    float s = 0.f;
    for (int e = 0; e < 256; e++) s = fmaf(W[j * 256 + e], in[b * 256 + e], s);
    out[t] = __fadd_rn(s, bias[j]);
}

// ---------------- host orchestration ----------------

static void run_edge_block(const float* xin, int C, int O,
                           const float* w, const float* g, const float* bta,
                           float* xout,
                           double* dist, double* xxp, int* idxp,
                           float* wT, float* ymax, double* stats)
{
    int C2 = 2 * C;
    xx_kernel<<<(Bc * Nc + 255) / 256, 256>>>(xin, xxp, C);
    dist_kernel<<<dim3(Nc / 32, Nc / 32, Bc), 256>>>(xin, xxp, dist, C);
    topk_kernel<<<Bc * Nc, 32>>>(dist, idxp);
    transpose_kernel<<<(O * C2 + 255) / 256, 256>>>(w, wT, O, C2);
    cudaMemsetAsync(stats, 0, 2 * O * sizeof(double), 0);
    size_t shm = (size_t)(C2 * Kc + C) * sizeof(float) + Kc * sizeof(int);
    edgeconv_kernel<<<dim3(Nc, Bc), O, shm>>>(xin, wT, idxp, ymax, stats, C, O);
    int total = Bc * Nc * O;
    bnapply_kernel<<<(total + 255) / 256, 256>>>(ymax, stats, g, bta, xout, O,
                                                 1.0 / (double)(Bc * Nc * Kc));
}

extern "C" void kernel_launch(void* const* d_in, const int* in_sizes, int n_in,
                              void* d_out, int out_size)
{
    const float* x   = (const float*)d_in[0];
    const float* w1  = (const float*)d_in[1];
    const float* w2  = (const float*)d_in[2];
    const float* w3  = (const float*)d_in[3];
    const float* w4  = (const float*)d_in[4];
    const float* w5  = (const float*)d_in[5];
    const float* lw1 = (const float*)d_in[6];
    const float* lw2 = (const float*)d_in[7];
    const float* lb2 = (const float*)d_in[8];
    const float* lw3 = (const float*)d_in[9];
    const float* lb3 = (const float*)d_in[10];
    const float* g1 = (const float*)d_in[11]; const float* b1 = (const float*)d_in[12];
    const float* g2 = (const float*)d_in[13]; const float* b2 = (const float*)d_in[14];
    const float* g3 = (const float*)d_in[15]; const float* b3 = (const float*)d_in[16];
    const float* g4 = (const float*)d_in[17]; const float* b4 = (const float*)d_in[18];
    const float* g5 = (const float*)d_in[19]; const float* b5 = (const float*)d_in[20];
    const float* g6 = (const float*)d_in[21]; const float* b6 = (const float*)d_in[22];
    const float* g7 = (const float*)d_in[23]; const float* b7 = (const float*)d_in[24];

    float *wT, *ymax, *x1b, *x2b, *x3b, *x4b, *z5, *pbuf, *h1, *h2;
    double *dist, *xxp, *stats;
    int* idxp;
    cudaGetSymbolAddress((void**)&dist,  g_distd);
    cudaGetSymbolAddress((void**)&xxp,   g_xxd);
    cudaGetSymbolAddress((void**)&idxp,  g_idx);
    cudaGetSymbolAddress((void**)&wT,    g_wT);
    cudaGetSymbolAddress((void**)&ymax,  g_ymax);
    cudaGetSymbolAddress((void**)&stats, g_statsd);
    cudaGetSymbolAddress((void**)&x1b,   g_x1);
    cudaGetSymbolAddress((void**)&x2b,   g_x2);
    cudaGetSymbolAddress((void**)&x3b,   g_x3);
    cudaGetSymbolAddress((void**)&x4b,   g_x4);
    cudaGetSymbolAddress((void**)&z5,    g_z5);
    cudaGetSymbolAddress((void**)&pbuf,  g_p);
    cudaGetSymbolAddress((void**)&h1,    g_h1);
    cudaGetSymbolAddress((void**)&h2,    g_h2);

    run_edge_block(x,   3,   64,  w1, g1, b1, x1b, dist, xxp, idxp, wT, ymax, stats);
    run_edge_block(x1b, 64,  64,  w2, g2, b2, x2b, dist, xxp, idxp, wT, ymax, stats);
    run_edge_block(x2b, 64,  128, w3, g3, b3, x3b, dist, xxp, idxp, wT, ymax, stats);
    run_edge_block(x3b, 128, 256, w4, g4, b4, x4b, dist, xxp, idxp, wT, ymax, stats);

    cudaMemsetAsync(stats, 0, 2 * EMBc * sizeof(double), 0);
    conv5_kernel<<<dim3(Nc / 64, EMBc / 64, Bc), 256>>>(w5, x1b, x2b, x3b, x4b, z5, stats);
    pool5_kernel<<<dim3(EMBc, Bc), 32>>>(z5, stats, g5, b5, pbuf);

    fc_bn_kernel<<<512, 64>>>(pbuf, lw1, nullptr, g6, b6, h1, 2 * EMBc, 512);
    fc_bn_kernel<<<256, 64>>>(h1, lw2, lb2, g7, b7, h2, 512, 256);
    fc3_kernel<<<1, 320>>>(h2, lw3, lb3, (float*)d_out);
}

// round 8
// speedup vs baseline: 1.7041x; 1.7041x over previous
#include <cuda_runtime.h>
#include <cstdint>
#include <math.h>

#define Bc 8
#define Nc 2048
#define Kc 20
#define EMBc 1024
#define EPSc 1e-5
#define SLOPEc 0.2f

// ---------------- scratch (static device globals; no allocation allowed) ----------------
__device__ float2 g_dist2[(size_t)Bc * Nc * Nc];   // 128 MB pd as double-float (hi,lo)
__device__ float2 g_xx2[Bc * Nc];
__device__ int    g_idx[Bc * Nc * Kc];
__device__ float  g_x1[Bc * 64 * Nc];
__device__ float  g_x2[Bc * 64 * Nc];
__device__ float  g_x3[Bc * 128 * Nc];
__device__ float  g_x4[Bc * 256 * Nc];
__device__ float  g_wT[256 * 512];
__device__ float  g_ymax[Bc * Nc * 256];           // [b][n][o] pre-BN max over k
__device__ double g_statsd[2 * EMBc];              // per-channel sum / sumsq (fp64, R5-proven)
__device__ float  g_z5[Bc * EMBc * Nc];            // 64 MB conv5 pre-BN output
__device__ float  g_p[Bc * 2 * EMBc];
__device__ float  g_h1[Bc * 512];
__device__ float  g_h2[Bc * 256];

// ---------------- double-float helpers (fp32 pipe only) ----------------
__device__ __forceinline__ void two_sum(float a, float b, float& s, float& e)
{
    s = __fadd_rn(a, b);
    float bp = __fsub_rn(s, a);
    e = __fadd_rn(__fsub_rn(a, __fsub_rn(s, bp)), __fsub_rn(b, bp));
}

// (ah,al) - (b.x,b.y), renormalized
__device__ __forceinline__ float2 dd_sub(float ah, float al, float2 b)
{
    float s1  = __fsub_rn(ah, b.x);
    float v   = __fsub_rn(s1, ah);
    float err = __fsub_rn(__fsub_rn(ah, __fsub_rn(s1, v)), __fadd_rn(b.x, v));
    err = __fadd_rn(err, __fsub_rn(al, b.y));
    float hi = __fadd_rn(s1, err);
    float lo = __fsub_rn(err, __fsub_rn(hi, s1));
    return make_float2(hi, lo);
}

__device__ __forceinline__ bool dd_gt(float2 a, float2 b)
{
    return (a.x > b.x) || (a.x == b.x && a.y > b.y);
}

// ---------------- kernels ----------------

// xx = sum_c x^2, exact in fp64 once per point (tiny), stored as (hi,lo)
__global__ void xx_kernel(const float* __restrict__ x, float2* __restrict__ xx2, int C)
{
    int i = blockIdx.x * blockDim.x + threadIdx.x;
    if (i >= Bc * Nc) return;
    int b = i / Nc, n = i % Nc;
    double s = 0.0;
    for (int c = 0; c < C; c++) {
        double v = (double)x[((size_t)b * C + c) * Nc + n];
        s += v * v;
    }
    float hi = (float)s;
    float lo = (float)(s - (double)hi);
    xx2[i] = make_float2(hi, lo);
}

// pd[b,n,m] = 2*dot - xx_n - xx_m as double-float; dot = fp32 FMA per 8-ch chunk
// + two-sum compensation across chunks. 64x64 tile, 256 threads, 4x4 micro-tile.
__global__ void dist_kernel(const float* __restrict__ x, const float2* __restrict__ xx2,
                            float2* __restrict__ dist, int C)
{
    __shared__ float sn[8][64];
    __shared__ float sm_[8][64];
    int b = blockIdx.z;
    int n0 = blockIdx.y * 64, m0 = blockIdx.x * 64;
    int t = threadIdx.x;
    int tx = t & 15, ty = t >> 4;
    float s[4][4], e[4][4];
#pragma unroll
    for (int i = 0; i < 4; i++)
#pragma unroll
        for (int j = 0; j < 4; j++) { s[i][j] = 0.f; e[i][j] = 0.f; }
    const float* xb = x + (size_t)b * C * Nc;

    for (int c0 = 0; c0 < C; c0 += 8) {
#pragma unroll
        for (int r = 0; r < 2; r++) {
            int ei = t + r * 256;
            int cc = ei >> 6, j = ei & 63;
            int c = c0 + cc;
            sn[cc][j]  = (c < C) ? xb[(size_t)c * Nc + n0 + j] : 0.f;
            sm_[cc][j] = (c < C) ? xb[(size_t)c * Nc + m0 + j] : 0.f;
        }
        __syncthreads();
        float f[4][4];
#pragma unroll
        for (int i = 0; i < 4; i++)
#pragma unroll
            for (int j = 0; j < 4; j++) f[i][j] = 0.f;
#pragma unroll
        for (int q = 0; q < 8; q++) {
            float4 nv = *(const float4*)&sn[q][ty * 4];
            float4 mv = *(const float4*)&sm_[q][tx * 4];
            float nn[4] = {nv.x, nv.y, nv.z, nv.w};
            float mm[4] = {mv.x, mv.y, mv.z, mv.w};
#pragma unroll
            for (int i = 0; i < 4; i++)
#pragma unroll
                for (int j = 0; j < 4; j++)
                    f[i][j] = fmaf(nn[i], mm[j], f[i][j]);
        }
#pragma unroll
        for (int i = 0; i < 4; i++)
#pragma unroll
            for (int j = 0; j < 4; j++) {
                float sh, er;
                two_sum(s[i][j], f[i][j], sh, er);
                s[i][j] = sh;
                e[i][j] = __fadd_rn(e[i][j], er);
            }
        __syncthreads();
    }
    int n = n0 + ty * 4, m = m0 + tx * 4;
    float2 xn[4], xm[4];
#pragma unroll
    for (int i = 0; i < 4; i++) { xn[i] = xx2[b * Nc + n + i]; xm[i] = xx2[b * Nc + m + i]; }
    float2* dr = dist + (size_t)b * Nc * Nc;
#pragma unroll
    for (int i = 0; i < 4; i++)
#pragma unroll
        for (int j = 0; j < 4; j++) {
            float dh, dl;
            two_sum(s[i][j], e[i][j], dh, dl);
            dh = __fmul_rn(dh, 2.f);         // exact
            dl = __fmul_rn(dl, 2.f);         // exact
            float2 r1 = dd_sub(dh, dl, xn[i]);
            float2 r2 = dd_sub(r1.x, r1.y, xm[j]);
            dr[(size_t)(n + i) * Nc + m + j] = r2;
        }
}

// top-20 per row over (hi,lo) keys: 256 threads, 8 register-resident keys each;
// 20 rounds of (local argmax -> warp argmax -> 8-warp argmax). Ties -> lowest index.
__global__ void topk_kernel(const float2* __restrict__ dist, int* __restrict__ idx)
{
    int row = blockIdx.x;                 // b*Nc + n
    int t = threadIdx.x;
    int lane = t & 31, wid = t >> 5;
    const float2* d = dist + (size_t)row * Nc;
    float2 v[8];
    int base = t * 8;
#pragma unroll
    for (int q = 0; q < 8; q++) v[q] = d[base + q];

    __shared__ float2 swv[8];
    __shared__ int    swi[8];
    __shared__ int    sbci;

    for (int kk = 0; kk < Kc; kk++) {
        float2 bv = v[0]; int bq = 0;
#pragma unroll
        for (int q = 1; q < 8; q++)
            if (dd_gt(v[q], bv)) { bv = v[q]; bq = q; }
        int bj = base + bq;
#pragma unroll
        for (int off = 16; off; off >>= 1) {
            float ox = __shfl_xor_sync(0xffffffffu, bv.x, off);
            float oy = __shfl_xor_sync(0xffffffffu, bv.y, off);
            int   oj = __shfl_xor_sync(0xffffffffu, bj,   off);
            if (ox > bv.x || (ox == bv.x && (oy > bv.y || (oy == bv.y && oj < bj)))) {
                bv = make_float2(ox, oy); bj = oj;
            }
        }
        if (lane == 0) { swv[wid] = bv; swi[wid] = bj; }
        __syncthreads();
        if (t == 0) {
            float2 Bv = swv[0]; int Bi = swi[0];
#pragma unroll
            for (int w = 1; w < 8; w++)
                if (swv[w].x > Bv.x ||
                    (swv[w].x == Bv.x && (swv[w].y > Bv.y ||
                     (swv[w].y == Bv.y && swi[w] < Bi)))) { Bv = swv[w]; Bi = swi[w]; }
            sbci = Bi;
            idx[(size_t)row * Kc + kk] = Bi;
        }
        __syncthreads();
        int win = sbci;
        if ((win >> 3) == t) v[win & 7] = make_float2(-INFINITY, -INFINITY);
    }
}

__global__ void transpose_kernel(const float* __restrict__ w, float* __restrict__ wT,
                                 int O, int C2)
{
    int t = blockIdx.x * blockDim.x + threadIdx.x;
    if (t < O * C2) { int o = t / C2, c = t % C2; wT[c * O + o] = w[t]; }
}

// fused: gather graph feature -> 1x1 conv (R5-exact) -> fp64 per-channel stats (R5-exact)
// -> max over k (pre-BN). block = (n, b), threads = O.
__global__ void edgeconv_kernel(const float* __restrict__ xin, const float* __restrict__ wT,
                                const int* __restrict__ idx, float* __restrict__ ymax,
                                double* __restrict__ stats, int C, int O)
{
    extern __shared__ float shm[];
    int n = blockIdx.x, b = blockIdx.y, t = threadIdx.x;
    int C2 = 2 * C;
    float* feat = shm;                // [C2][Kc]
    float* ctr  = shm + C2 * Kc;      // [C]
    int*   sidx = (int*)(ctr + C);    // [Kc]

    if (t < Kc) sidx[t] = idx[((size_t)b * Nc + n) * Kc + t];
    for (int c = t; c < C; c += blockDim.x)
        ctr[c] = xin[((size_t)b * C + c) * Nc + n];
    __syncthreads();
    for (int e = t; e < C * Kc; e += blockDim.x) {
        int c = e / Kc, k = e - c * Kc;
        float cv = ctr[c];
        float nv = xin[((size_t)b * C + c) * Nc + sidx[k]];
        feat[c * Kc + k]       = __fsub_rn(nv, cv);  // channels [0,C): nbr - ctr
        feat[(C + c) * Kc + k] = cv;                 // channels [C,2C): ctr
    }
    __syncthreads();

    float acc[Kc];
#pragma unroll
    for (int k = 0; k < Kc; k++) acc[k] = 0.f;

#pragma unroll 2
    for (int c2 = 0; c2 < C2; c2++) {
        float w = wT[c2 * O + t];
        const float4* fr = reinterpret_cast<const float4*>(feat + c2 * Kc);
#pragma unroll
        for (int q = 0; q < Kc / 4; q++) {
            float4 f = fr[q];
            acc[4 * q + 0] = fmaf(w, f.x, acc[4 * q + 0]);
            acc[4 * q + 1] = fmaf(w, f.y, acc[4 * q + 1]);
            acc[4 * q + 2] = fmaf(w, f.z, acc[4 * q + 2]);
            acc[4 * q + 3] = fmaf(w, f.w, acc[4 * q + 3]);
        }
    }

    float m = acc[0];
    double s = 0.0, ss = 0.0;
#pragma unroll
    for (int k = 0; k < Kc; k++) {
        m = fmaxf(m, acc[k]);
        double a = (double)acc[k];
        s += a;
        ss += a * a;
    }
    ymax[((size_t)b * Nc + n) * O + t] = m;   // coalesced across o
    atomicAdd(&stats[t], s);
    atomicAdd(&stats[O + t], ss);
}

// BN + lrelu on max-pooled values, smem-tile transpose [b][n][o] -> [b][o][n]
// (m, r derived from fp64 stats exactly as R5's bnapply)
__global__ void bnapply_kernel(const float* __restrict__ ymax, const double* __restrict__ stats,
                               const float* __restrict__ g, const float* __restrict__ bta,
                               float* __restrict__ xout, int O, double invcnt)
{
    __shared__ float tile[32][33];
    int b  = blockIdx.z;
    int o0 = blockIdx.y * 32;
    int n0 = blockIdx.x * 32;
    int tx = threadIdx.x, ty = threadIdx.y;   // 32 x 8
    int o = o0 + tx;
    double mean = stats[o] * invcnt;
    double var  = stats[O + o] * invcnt - mean * mean;
    float m = (float)mean;
    float r = (float)rsqrt(var + EPSc);
    float gg = g[o], bb = bta[o];
#pragma unroll
    for (int rr = 0; rr < 4; rr++) {
        int n = n0 + ty + rr * 8;
        float vv = ymax[((size_t)b * Nc + n) * O + o];
        float y = __fadd_rn(__fmul_rn(__fmul_rn(__fsub_rn(vv, m), r), gg), bb);
        tile[ty + rr * 8][tx] = (y >= 0.f) ? y : SLOPEc * y;
    }
    __syncthreads();
#pragma unroll
    for (int rr = 0; rr < 4; rr++) {
        int oo = o0 + ty + rr * 8;
        xout[((size_t)b * O + oo) * Nc + n0 + tx] = tile[tx][ty + rr * 8];
    }
}

// conv5: z[b,o,n] = sum_c w5[o,c]*cat[b,c,n]; fp64 stats via smem reduce + atomics (R5-exact)
__global__ void conv5_kernel(const float* __restrict__ w5,
                             const float* __restrict__ x1, const float* __restrict__ x2,
                             const float* __restrict__ x3, const float* __restrict__ x4,
                             float* __restrict__ z, double* __restrict__ stats)
{
    __shared__ float As[16][68];
    __shared__ float Bs[16][64];
    __shared__ double rs[64], rss[64];
    int b  = blockIdx.z;
    int o0 = blockIdx.y * 64;
    int n0 = blockIdx.x * 64;
    int t = threadIdx.x;
    int tx = t & 15, ty = t >> 4;
    float acc[4][4];
#pragma unroll
    for (int i = 0; i < 4; i++)
#pragma unroll
        for (int j = 0; j < 4; j++) acc[i][j] = 0.f;

    for (int c0 = 0; c0 < 512; c0 += 16) {
#pragma unroll
        for (int r = 0; r < 4; r++) {
            int e = t + r * 256;
            int oo = e >> 4, cc = e & 15;
            As[cc][oo] = w5[(size_t)(o0 + oo) * 512 + c0 + cc];
            int cc2 = e >> 6, jj = e & 63;
            int ch = c0 + cc2;
            const float* src; int cl, Cb;
            if (ch < 64)       { src = x1; cl = ch;       Cb = 64;  }
            else if (ch < 128) { src = x2; cl = ch - 64;  Cb = 64;  }
            else if (ch < 256) { src = x3; cl = ch - 128; Cb = 128; }
            else               { src = x4; cl = ch - 256; Cb = 256; }
            Bs[cc2][jj] = src[((size_t)b * Cb + cl) * Nc + n0 + jj];
        }
        __syncthreads();
#pragma unroll
        for (int cc = 0; cc < 16; cc++) {
            float4 av4 = *(const float4*)&As[cc][ty * 4];
            float4 bv4 = *(const float4*)&Bs[cc][tx * 4];
            float av[4] = {av4.x, av4.y, av4.z, av4.w};
            float bv[4] = {bv4.x, bv4.y, bv4.z, bv4.w};
#pragma unroll
            for (int i = 0; i < 4; i++)
#pragma unroll
                for (int j = 0; j < 4; j++)
                    acc[i][j] = fmaf(av[i], bv[j], acc[i][j]);
        }
        __syncthreads();
    }
    if (t < 64) { rs[t] = 0.0; rss[t] = 0.0; }
    __syncthreads();
#pragma unroll
    for (int i = 0; i < 4; i++) {
        int o = o0 + ty * 4 + i;
        double s = 0.0, ss = 0.0;
#pragma unroll
        for (int j = 0; j < 4; j++) { double v = (double)acc[i][j]; s += v; ss += v * v; }
        atomicAdd(&rs[ty * 4 + i], s);
        atomicAdd(&rss[ty * 4 + i], ss);
        float4 v4 = make_float4(acc[i][0], acc[i][1], acc[i][2], acc[i][3]);
        *reinterpret_cast<float4*>(&z[((size_t)b * EMBc + o) * Nc + n0 + tx * 4]) = v4;
    }
    __syncthreads();
    if (t < 64) {
        atomicAdd(&stats[o0 + t], rs[t]);
        atomicAdd(&stats[EMBc + o0 + t], rss[t]);
    }
}

// BN + lrelu + max/mean pooling over n for one (b, o) per warp (fp64 stats, R5-exact)
__global__ void pool5_kernel(const float* __restrict__ z, const double* __restrict__ stats,
                             const float* __restrict__ g, const float* __restrict__ bta,
                             float* __restrict__ p)
{
    int o = blockIdx.x, b = blockIdx.y, lane = threadIdx.x;
    const double inv = 1.0 / (double)(Bc * Nc);
    double mean = stats[o] * inv;
    double var  = stats[EMBc + o] * inv - mean * mean;
    float m = (float)mean;
    float r = (float)rsqrt(var + EPSc);
    float gg = g[o], bb = bta[o];
    const float* row = z + ((size_t)b * EMBc + o) * Nc;
    float mx = -INFINITY, sm = 0.f;
    for (int j = lane; j < Nc; j += 32) {
        float v = __fadd_rn(__fmul_rn(__fmul_rn(__fsub_rn(row[j], m), r), gg), bb);
        v = (v >= 0.f) ? v : SLOPEc * v;
        mx = fmaxf(mx, v);
        sm += v;
    }
    for (int off = 16; off; off >>= 1) {
        mx = fmaxf(mx, __shfl_xor_sync(0xffffffffu, mx, off));
        sm += __shfl_xor_sync(0xffffffffu, sm, off);
    }
    if (lane == 0) {
        p[b * 2 * EMBc + o] = mx;
        p[b * 2 * EMBc + EMBc + o] = sm * (1.0f / Nc);
    }
}

// fully-connected + batch BN (over B=8, fp64 moments over 8 values) + lrelu
__global__ void fc_bn_kernel(const float* __restrict__ in, const float* __restrict__ W,
                             const float* __restrict__ bias, const float* __restrict__ g,
                             const float* __restrict__ bta, float* __restrict__ out,
                             int Cin, int Cout)
{
    int j = blockIdx.x, t = threadIdx.x;
    float a[Bc];
#pragma unroll
    for (int b_ = 0; b_ < Bc; b_++) a[b_] = 0.f;
    for (int e = t; e < Cin; e += 64) {
        float w = W[(size_t)j * Cin + e];
#pragma unroll
        for (int b_ = 0; b_ < Bc; b_++) a[b_] = fmaf(w, in[b_ * Cin + e], a[b_]);
    }
    __shared__ float red[64][Bc];
#pragma unroll
    for (int b_ = 0; b_ < Bc; b_++) red[t][b_] = a[b_];
    __syncthreads();
    for (int s = 32; s > 0; s >>= 1) {
        if (t < s) {
#pragma unroll
            for (int b_ = 0; b_ < Bc; b_++) red[t][b_] += red[t + s][b_];
        }
        __syncthreads();
    }
    if (t < Bc) {
        float bb = bias ? bias[j] : 0.f;
        float vals[Bc];
        double mean = 0.0;
#pragma unroll
        for (int b_ = 0; b_ < Bc; b_++) { vals[b_] = red[0][b_] + bb; mean += (double)vals[b_]; }
        mean *= (1.0 / Bc);
        double var = 0.0;
#pragma unroll
        for (int b_ = 0; b_ < Bc; b_++) { double d = (double)vals[b_] - mean; var += d * d; }
        var *= (1.0 / Bc);
        float m = (float)mean;
        float r = (float)rsqrt(var + EPSc);
        float y = __fadd_rn(__fmul_rn(__fmul_rn(__fsub_rn(vals[t], m), r), g[j]), bta[j]);
        out[t * Cout + j] = (y >= 0.f) ? y : SLOPEc * y;
    }
}

__global__ void fc3_kernel(const float* __restrict__ in, const float* __restrict__ W,
                           const float* __restrict__ bias, float* __restrict__ out)
{
    int t = threadIdx.x;
    if (t >= Bc * 40) return;
    int b = t / 40, j = t % 40;
    float s = 0.f;
    for (int e = 0; e < 256; e++) s = fmaf(W[j * 256 + e], in[b * 256 + e], s);
    out[t] = __fadd_rn(s, bias[j]);
}

// ---------------- host orchestration ----------------

static void run_edge_block(const float* xin, int C, int O,
                           const float* w, const float* g, const float* bta,
                           float* xout,
                           float2* dist, float2* xxp, int* idxp,
                           float* wT, float* ymax, double* stats)
{
    int C2 = 2 * C;
    xx_kernel<<<(Bc * Nc + 255) / 256, 256>>>(xin, xxp, C);
    dist_kernel<<<dim3(Nc / 64, Nc / 64, Bc), 256>>>(xin, xxp, dist, C);
    topk_kernel<<<Bc * Nc, 256>>>(dist, idxp);
    transpose_kernel<<<(O * C2 + 255) / 256, 256>>>(w, wT, O, C2);
    cudaMemsetAsync(stats, 0, 2 * O * sizeof(double), 0);
    size_t shm = (size_t)(C2 * Kc + C) * sizeof(float) + Kc * sizeof(int);
    edgeconv_kernel<<<dim3(Nc, Bc), O, shm>>>(xin, wT, idxp, ymax, stats, C, O);
    bnapply_kernel<<<dim3(Nc / 32, O / 32, Bc), dim3(32, 8)>>>(ymax, stats, g, bta, xout, O,
                                                               1.0 / (double)(Bc * Nc * Kc));
}

extern "C" void kernel_launch(void* const* d_in, const int* in_sizes, int n_in,
                              void* d_out, int out_size)
{
    const float* x   = (const float*)d_in[0];
    const float* w1  = (const float*)d_in[1];
    const float* w2  = (const float*)d_in[2];
    const float* w3  = (const float*)d_in[3];
    const float* w4  = (const float*)d_in[4];
    const float* w5  = (const float*)d_in[5];
    const float* lw1 = (const float*)d_in[6];
    const float* lw2 = (const float*)d_in[7];
    const float* lb2 = (const float*)d_in[8];
    const float* lw3 = (const float*)d_in[9];
    const float* lb3 = (const float*)d_in[10];
    const float* g1 = (const float*)d_in[11]; const float* b1 = (const float*)d_in[12];
    const float* g2 = (const float*)d_in[13]; const float* b2 = (const float*)d_in[14];
    const float* g3 = (const float*)d_in[15]; const float* b3 = (const float*)d_in[16];
    const float* g4 = (const float*)d_in[17]; const float* b4 = (const float*)d_in[18];
    const float* g5 = (const float*)d_in[19]; const float* b5 = (const float*)d_in[20];
    const float* g6 = (const float*)d_in[21]; const float* b6 = (const float*)d_in[22];
    const float* g7 = (const float*)d_in[23]; const float* b7 = (const float*)d_in[24];

    float *wT, *ymax, *x1b, *x2b, *x3b, *x4b, *z5, *pbuf, *h1, *h2;
    float2 *dist, *xxp;
    double* stats;
    int* idxp;
    cudaGetSymbolAddress((void**)&dist,  g_dist2);
    cudaGetSymbolAddress((void**)&xxp,   g_xx2);
    cudaGetSymbolAddress((void**)&idxp,  g_idx);
    cudaGetSymbolAddress((void**)&wT,    g_wT);
    cudaGetSymbolAddress((void**)&ymax,  g_ymax);
    cudaGetSymbolAddress((void**)&stats, g_statsd);
    cudaGetSymbolAddress((void**)&x1b,   g_x1);
    cudaGetSymbolAddress((void**)&x2b,   g_x2);
    cudaGetSymbolAddress((void**)&x3b,   g_x3);
    cudaGetSymbolAddress((void**)&x4b,   g_x4);
    cudaGetSymbolAddress((void**)&z5,    g_z5);
    cudaGetSymbolAddress((void**)&pbuf,  g_p);
    cudaGetSymbolAddress((void**)&h1,    g_h1);
    cudaGetSymbolAddress((void**)&h2,    g_h2);

    run_edge_block(x,   3,   64,  w1, g1, b1, x1b, dist, xxp, idxp, wT, ymax, stats);
    run_edge_block(x1b, 64,  64,  w2, g2, b2, x2b, dist, xxp, idxp, wT, ymax, stats);
    run_edge_block(x2b, 64,  128, w3, g3, b3, x3b, dist, xxp, idxp, wT, ymax, stats);
    run_edge_block(x3b, 128, 256, w4, g4, b4, x4b, dist, xxp, idxp, wT, ymax, stats);

    cudaMemsetAsync(stats, 0, 2 * EMBc * sizeof(double), 0);
    conv5_kernel<<<dim3(Nc / 64, EMBc / 64, Bc), 256>>>(w5, x1b, x2b, x3b, x4b, z5, stats);
    pool5_kernel<<<dim3(EMBc, Bc), 32>>>(z5, stats, g5, b5, pbuf);

    fc_bn_kernel<<<512, 64>>>(pbuf, lw1, nullptr, g6, b6, h1, 2 * EMBc, 512);
    fc_bn_kernel<<<256, 64>>>(h1, lw2, lb2, g7, b7, h2, 512, 256);
    fc3_kernel<<<1, 320>>>(h2, lw3, lb3, (float*)d_out);
}

// round 10
// speedup vs baseline: 1.8843x; 1.1057x over previous
#include <cuda_runtime.h>
#include <cstdint>
#include <math.h>

#define Bc 8
#define Nc 2048
#define Kc 20
#define EMBc 1024
#define EPSc 1e-5
#define SLOPEc 0.2f

typedef unsigned long long u64;

// ---------------- packed f32x2 helpers (exact dual IEEE fp32 ops, 2x fma throughput) ----
__device__ __forceinline__ u64 pack2(float lo, float hi)
{
    u64 r; asm("mov.b64 %0, {%1, %2};" : "=l"(r) : "f"(lo), "f"(hi)); return r;
}
__device__ __forceinline__ void unpack2(u64 v, float& lo, float& hi)
{
    asm("mov.b64 {%0, %1}, %2;" : "=f"(lo), "=f"(hi) : "l"(v));
}
__device__ __forceinline__ u64 fma2(u64 a, u64 b, u64 c)
{
    u64 d; asm("fma.rn.f32x2 %0, %1, %2, %3;" : "=l"(d) : "l"(a), "l"(b), "l"(c)); return d;
}
__device__ __forceinline__ u64 add2(u64 a, u64 b)
{
    u64 d; asm("add.rn.f32x2 %0, %1, %2;" : "=l"(d) : "l"(a), "l"(b)); return d;
}
// exact packed subtract: a - b == fma(b, -1, a) (exactly rounded)
__device__ __forceinline__ u64 sub2(u64 a, u64 b)
{
    return fma2(b, 0xBF800000BF800000ull, a);
}

// ---------------- scratch (static device globals; no allocation allowed) ----------------
__device__ float2 g_dist2[(size_t)Bc * Nc * Nc];   // 128 MB pd as double-float (hi,lo)
__device__ float2 g_xx2[Bc * Nc];
__device__ int    g_idx[Bc * Nc * Kc];
__device__ float  g_x1[Bc * 64 * Nc];
__device__ float  g_x2[Bc * 64 * Nc];
__device__ float  g_x3[Bc * 128 * Nc];
__device__ float  g_x4[Bc * 256 * Nc];
__device__ float  g_wT[90496];                     // all 4 transposed weights, segmented
__device__ float  g_ymax[Bc * Nc * 256];           // [b][n][o] pre-BN max over k
__device__ double g_statsd[3072];                  // segmented per-layer stats (fp64)
__device__ float  g_z5[Bc * EMBc * Nc];            // 64 MB conv5 pre-BN output
__device__ float  g_p[Bc * 2 * EMBc];
__device__ float  g_h1[Bc * 512];
__device__ float  g_h2[Bc * 256];

// segment offsets
#define WT_OFF1 0
#define WT_OFF2 384
#define WT_OFF3 8576
#define WT_OFF4 24960
#define ST_OFF1 0
#define ST_OFF2 128
#define ST_OFF3 256
#define ST_OFF4 512
#define ST_OFF5 1024

// ---------------- double-float helpers (fp32 pipe only) ----------------
__device__ __forceinline__ void two_sum(float a, float b, float& s, float& e)
{
    s = __fadd_rn(a, b);
    float bp = __fsub_rn(s, a);
    e = __fadd_rn(__fsub_rn(a, __fsub_rn(s, bp)), __fsub_rn(b, bp));
}

__device__ __forceinline__ float2 dd_sub(float ah, float al, float2 b)
{
    float s1  = __fsub_rn(ah, b.x);
    float v   = __fsub_rn(s1, ah);
    float err = __fsub_rn(__fsub_rn(ah, __fsub_rn(s1, v)), __fadd_rn(b.x, v));
    err = __fadd_rn(err, __fsub_rn(al, b.y));
    float hi = __fadd_rn(s1, err);
    float lo = __fsub_rn(err, __fsub_rn(hi, s1));
    return make_float2(hi, lo);
}

__device__ __forceinline__ bool dd_gt(float2 a, float2 b)
{
    return (a.x > b.x) || (a.x == b.x && a.y > b.y);
}

// ---------------- kernels ----------------

// transpose all 4 edge-conv weights into wT segments (one up-front launch)
// w1:(64,6) w2:(64,128) w3:(128,128) w4:(256,256)
__global__ void transpose_all(const float* __restrict__ w1, const float* __restrict__ w2,
                              const float* __restrict__ w3, const float* __restrict__ w4,
                              float* __restrict__ wT)
{
    int t = blockIdx.x * blockDim.x + threadIdx.x;
    const float* w; int O, C2, base, li;
    if (t < 384)        { w = w1; O = 64;  C2 = 6;   base = WT_OFF1; li = t; }
    else if (t < 8576)  { w = w2; O = 64;  C2 = 128; base = WT_OFF2; li = t - 384; }
    else if (t < 24960) { w = w3; O = 128; C2 = 128; base = WT_OFF3; li = t - 8576; }
    else if (t < 90496) { w = w4; O = 256; C2 = 256; base = WT_OFF4; li = t - 24960; }
    else return;
    int o = li / C2, c = li % C2;
    wT[base + c * O + o] = w[li];
}

__global__ void zerostats_kernel(double* __restrict__ stats)
{
    int t = blockIdx.x * blockDim.x + threadIdx.x;
    if (t < 3072) stats[t] = 0.0;
}

// xx = sum_c x^2, exact in fp64 once per point (tiny), stored as (hi,lo)
__global__ void xx_kernel(const float* __restrict__ x, float2* __restrict__ xx2, int C)
{
    int i = blockIdx.x * blockDim.x + threadIdx.x;
    if (i >= Bc * Nc) return;
    int b = i / Nc, n = i % Nc;
    double s = 0.0;
    for (int c = 0; c < C; c++) {
        double v = (double)x[((size_t)b * C + c) * Nc + n];
        s += v * v;
    }
    float hi = (float)s;
    float lo = (float)(s - (double)hi);
    xx2[i] = make_float2(hi, lo);
}

// pd = 2*dot - xx_n - xx_m as double-float; fp32 FMA per 8-ch chunk + two-sum
// compensation across chunks — all packed f32x2 (bit-identical per lane to scalar).
__global__ void dist_kernel(const float* __restrict__ x, const float2* __restrict__ xx2,
                            float2* __restrict__ dist, int C)
{
    __shared__ float sn[8][64];
    __shared__ float sm_[8][64];
    int b = blockIdx.z;
    int n0 = blockIdx.y * 64, m0 = blockIdx.x * 64;
    int t = threadIdx.x;
    int tx = t & 15, ty = t >> 4;
    u64 s2[4][2], e2[4][2];
#pragma unroll
    for (int i = 0; i < 4; i++)
#pragma unroll
        for (int jp = 0; jp < 2; jp++) { s2[i][jp] = 0ull; e2[i][jp] = 0ull; }
    const float* xb = x + (size_t)b * C * Nc;

    for (int c0 = 0; c0 < C; c0 += 8) {
#pragma unroll
        for (int r = 0; r < 2; r++) {
            int ei = t + r * 256;
            int cc = ei >> 6, j = ei & 63;
            int c = c0 + cc;
            sn[cc][j]  = (c < C) ? xb[(size_t)c * Nc + n0 + j] : 0.f;
            sm_[cc][j] = (c < C) ? xb[(size_t)c * Nc + m0 + j] : 0.f;
        }
        __syncthreads();
        u64 f2[4][2];
#pragma unroll
        for (int i = 0; i < 4; i++) { f2[i][0] = 0ull; f2[i][1] = 0ull; }
#pragma unroll
        for (int q = 0; q < 8; q++) {
            float4 nv = *(const float4*)&sn[q][ty * 4];
            float4 mv = *(const float4*)&sm_[q][tx * 4];
            u64 m01 = pack2(mv.x, mv.y);
            u64 m23 = pack2(mv.z, mv.w);
            float nn[4] = {nv.x, nv.y, nv.z, nv.w};
#pragma unroll
            for (int i = 0; i < 4; i++) {
                u64 np = pack2(nn[i], nn[i]);
                f2[i][0] = fma2(np, m01, f2[i][0]);
                f2[i][1] = fma2(np, m23, f2[i][1]);
            }
        }
        // packed two-sum merge (same branchless formula as scalar two_sum)
#pragma unroll
        for (int i = 0; i < 4; i++)
#pragma unroll
            for (int jp = 0; jp < 2; jp++) {
                u64 tt = add2(s2[i][jp], f2[i][jp]);
                u64 bp = sub2(tt, s2[i][jp]);
                u64 ea = sub2(s2[i][jp], sub2(tt, bp));
                u64 eb = sub2(f2[i][jp], bp);
                e2[i][jp] = add2(e2[i][jp], add2(ea, eb));
                s2[i][jp] = tt;
            }
        __syncthreads();
    }
    int n = n0 + ty * 4, m = m0 + tx * 4;
    float s[4][4], e[4][4];
#pragma unroll
    for (int i = 0; i < 4; i++) {
        unpack2(s2[i][0], s[i][0], s[i][1]);
        unpack2(s2[i][1], s[i][2], s[i][3]);
        unpack2(e2[i][0], e[i][0], e[i][1]);
        unpack2(e2[i][1], e[i][2], e[i][3]);
    }
    float2 xn[4], xm[4];
#pragma unroll
    for (int i = 0; i < 4; i++) { xn[i] = xx2[b * Nc + n + i]; xm[i] = xx2[b * Nc + m + i]; }
    float2* dr = dist + (size_t)b * Nc * Nc;
#pragma unroll
    for (int i = 0; i < 4; i++)
#pragma unroll
        for (int j = 0; j < 4; j++) {
            float dh, dl;
            two_sum(s[i][j], e[i][j], dh, dl);
            dh = __fmul_rn(dh, 2.f);
            dl = __fmul_rn(dl, 2.f);
            float2 r1 = dd_sub(dh, dl, xn[i]);
            float2 r2 = dd_sub(r1.x, r1.y, xm[j]);
            dr[(size_t)(n + i) * Nc + m + j] = r2;
        }
}

// top-20 per row over (hi,lo) keys: 256 threads, 8 register-resident keys each.
__global__ void topk_kernel(const float2* __restrict__ dist, int* __restrict__ idx)
{
    int row = blockIdx.x;
    int t = threadIdx.x;
    int lane = t & 31, wid = t >> 5;
    const float2* d = dist + (size_t)row * Nc;
    float2 v[8];
    int base = t * 8;
#pragma unroll
    for (int q = 0; q < 8; q++) v[q] = d[base + q];

    __shared__ float2 swv[8];
    __shared__ int    swi[8];
    __shared__ int    sbci;

    for (int kk = 0; kk < Kc; kk++) {
        float2 bv = v[0]; int bq = 0;
#pragma unroll
        for (int q = 1; q < 8; q++)
            if (dd_gt(v[q], bv)) { bv = v[q]; bq = q; }
        int bj = base + bq;
#pragma unroll
        for (int off = 16; off; off >>= 1) {
            float ox = __shfl_xor_sync(0xffffffffu, bv.x, off);
            float oy = __shfl_xor_sync(0xffffffffu, bv.y, off);
            int   oj = __shfl_xor_sync(0xffffffffu, bj,   off);
            if (ox > bv.x || (ox == bv.x && (oy > bv.y || (oy == bv.y && oj < bj)))) {
                bv = make_float2(ox, oy); bj = oj;
            }
        }
        if (lane == 0) { swv[wid] = bv; swi[wid] = bj; }
        __syncthreads();
        if (t == 0) {
            float2 Bv = swv[0]; int Bi = swi[0];
#pragma unroll
            for (int w = 1; w < 8; w++)
                if (swv[w].x > Bv.x ||
                    (swv[w].x == Bv.x && (swv[w].y > Bv.y ||
                     (swv[w].y == Bv.y && swi[w] < Bi)))) { Bv = swv[w]; Bi = swi[w]; }
            sbci = Bi;
            idx[(size_t)row * Kc + kk] = Bi;
        }
        __syncthreads();
        int win = sbci;
        if ((win >> 3) == t) v[win & 7] = make_float2(-INFINITY, -INFINITY);
    }
}

// fused: gather graph feature -> 1x1 conv (packed f32x2, bit-identical chains) ->
// fp64 per-channel stats -> max over k (pre-BN). block = (n, b), threads = O.
__global__ void edgeconv_kernel(const float* __restrict__ xin, const float* __restrict__ wT,
                                const int* __restrict__ idx, float* __restrict__ ymax,
                                double* __restrict__ stats, int C, int O)
{
    extern __shared__ float shm[];
    int n = blockIdx.x, b = blockIdx.y, t = threadIdx.x;
    int C2 = 2 * C;
    float* feat = shm;                // [C2][Kc]
    float* ctr  = shm + C2 * Kc;      // [C]
    int*   sidx = (int*)(ctr + C);    // [Kc]

    if (t < Kc) sidx[t] = idx[((size_t)b * Nc + n) * Kc + t];
    for (int c = t; c < C; c += blockDim.x)
        ctr[c] = xin[((size_t)b * C + c) * Nc + n];
    __syncthreads();
    for (int e = t; e < C * Kc; e += blockDim.x) {
        int c = e / Kc, k = e - c * Kc;
        float cv = ctr[c];
        float nv = xin[((size_t)b * C + c) * Nc + sidx[k]];
        feat[c * Kc + k]       = __fsub_rn(nv, cv);
        feat[(C + c) * Kc + k] = cv;
    }
    __syncthreads();

    u64 acc2[Kc / 2];
#pragma unroll
    for (int p = 0; p < Kc / 2; p++) acc2[p] = 0ull;

#pragma unroll 2
    for (int c2 = 0; c2 < C2; c2++) {
        float w = wT[c2 * O + t];
        u64 wp = pack2(w, w);
        const u64* fr2 = reinterpret_cast<const u64*>(feat + c2 * Kc);
#pragma unroll
        for (int p = 0; p < Kc / 2; p++)
            acc2[p] = fma2(fr2[p], wp, acc2[p]);
    }

    float acc[Kc];
#pragma unroll
    for (int p = 0; p < Kc / 2; p++) unpack2(acc2[p], acc[2 * p], acc[2 * p + 1]);

    float m = acc[0];
    double s = 0.0, ss = 0.0;
#pragma unroll
    for (int k = 0; k < Kc; k++) {
        m = fmaxf(m, acc[k]);
        double a = (double)acc[k];
        s += a;
        ss += a * a;
    }
    ymax[((size_t)b * Nc + n) * O + t] = m;
    atomicAdd(&stats[t], s);
    atomicAdd(&stats[O + t], ss);
}

// BN + lrelu on max-pooled values, smem-tile transpose [b][n][o] -> [b][o][n]
__global__ void bnapply_kernel(const float* __restrict__ ymax, const double* __restrict__ stats,
                               const float* __restrict__ g, const float* __restrict__ bta,
                               float* __restrict__ xout, int O, double invcnt)
{
    __shared__ float tile[32][33];
    int b  = blockIdx.z;
    int o0 = blockIdx.y * 32;
    int n0 = blockIdx.x * 32;
    int tx = threadIdx.x, ty = threadIdx.y;   // 32 x 8
    int o = o0 + tx;
    double mean = stats[o] * invcnt;
    double var  = stats[O + o] * invcnt - mean * mean;
    float m = (float)mean;
    float r = (float)rsqrt(var + EPSc);
    float gg = g[o], bb = bta[o];
#pragma unroll
    for (int rr = 0; rr < 4; rr++) {
        int n = n0 + ty + rr * 8;
        float vv = ymax[((size_t)b * Nc + n) * O + o];
        float y = __fadd_rn(__fmul_rn(__fmul_rn(__fsub_rn(vv, m), r), gg), bb);
        tile[ty + rr * 8][tx] = (y >= 0.f) ? y : SLOPEc * y;
    }
    __syncthreads();
#pragma unroll
    for (int rr = 0; rr < 4; rr++) {
        int oo = o0 + ty + rr * 8;
        xout[((size_t)b * O + oo) * Nc + n0 + tx] = tile[tx][ty + rr * 8];
    }
}

// conv5 (packed f32x2, identical chains) + fp64 stats via smem reduce + atomics
__global__ void conv5_kernel(const float* __restrict__ w5,
                             const float* __restrict__ x1, const float* __restrict__ x2,
                             const float* __restrict__ x3, const float* __restrict__ x4,
                             float* __restrict__ z, double* __restrict__ stats)
{
    __shared__ float As[16][68];
    __shared__ float Bs[16][64];
    __shared__ double rs[64], rss[64];
    int b  = blockIdx.z;
    int o0 = blockIdx.y * 64;
    int n0 = blockIdx.x * 64;
    int t = threadIdx.x;
    int tx = t & 15, ty = t >> 4;
    u64 acc2[4][2];
#pragma unroll
    for (int i = 0; i < 4; i++) { acc2[i][0] = 0ull; acc2[i][1] = 0ull; }

    for (int c0 = 0; c0 < 512; c0 += 16) {
#pragma unroll
        for (int r = 0; r < 4; r++) {
            int e = t + r * 256;
            int oo = e >> 4, cc = e & 15;
            As[cc][oo] = w5[(size_t)(o0 + oo) * 512 + c0 + cc];
            int cc2 = e >> 6, jj = e & 63;
            int ch = c0 + cc2;
            const float* src; int cl, Cb;
            if (ch < 64)       { src = x1; cl = ch;       Cb = 64;  }
            else if (ch < 128) { src = x2; cl = ch - 64;  Cb = 64;  }
            else if (ch < 256) { src = x3; cl = ch - 128; Cb = 128; }
            else               { src = x4; cl = ch - 256; Cb = 256; }
            Bs[cc2][jj] = src[((size_t)b * Cb + cl) * Nc + n0 + jj];
        }
        __syncthreads();
#pragma unroll
        for (int cc = 0; cc < 16; cc++) {
            float4 av4 = *(const float4*)&As[cc][ty * 4];
            float4 bv4 = *(const float4*)&Bs[cc][tx * 4];
            u64 b01 = pack2(bv4.x, bv4.y);
            u64 b23 = pack2(bv4.z, bv4.w);
            float av[4] = {av4.x, av4.y, av4.z, av4.w};
#pragma unroll
            for (int i = 0; i < 4; i++) {
                u64 ap = pack2(av[i], av[i]);
                acc2[i][0] = fma2(ap, b01, acc2[i][0]);
                acc2[i][1] = fma2(ap, b23, acc2[i][1]);
            }
        }
        __syncthreads();
    }
    float acc[4][4];
#pragma unroll
    for (int i = 0; i < 4; i++) {
        unpack2(acc2[i][0], acc[i][0], acc[i][1]);
        unpack2(acc2[i][1], acc[i][2], acc[i][3]);
    }
    if (t < 64) { rs[t] = 0.0; rss[t] = 0.0; }
    __syncthreads();
#pragma unroll
    for (int i = 0; i < 4; i++) {
        int o = o0 + ty * 4 + i;
        double s = 0.0, ss = 0.0;
#pragma unroll
        for (int j = 0; j < 4; j++) { double v = (double)acc[i][j]; s += v; ss += v * v; }
        atomicAdd(&rs[ty * 4 + i], s);
        atomicAdd(&rss[ty * 4 + i], ss);
        float4 v4 = make_float4(acc[i][0], acc[i][1], acc[i][2], acc[i][3]);
        *reinterpret_cast<float4*>(&z[((size_t)b * EMBc + o) * Nc + n0 + tx * 4]) = v4;
    }
    __syncthreads();
    if (t < 64) {
        atomicAdd(&stats[o0 + t], rs[t]);
        atomicAdd(&stats[EMBc + o0 + t], rss[t]);
    }
}

// BN + lrelu + max/mean pooling over n for one (b, o) per warp
__global__ void pool5_kernel(const float* __restrict__ z, const double* __restrict__ stats,
                             const float* __restrict__ g, const float* __restrict__ bta,
                             float* __restrict__ p)
{
    int o = blockIdx.x, b = blockIdx.y, lane = threadIdx.x;
    const double inv = 1.0 / (double)(Bc * Nc);
    double mean = stats[o] * inv;
    double var  = stats[EMBc + o] * inv - mean * mean;
    float m = (float)mean;
    float r = (float)rsqrt(var + EPSc);
    float gg = g[o], bb = bta[o];
    const float* row = z + ((size_t)b * EMBc + o) * Nc;
    float mx = -INFINITY, sm = 0.f;
    for (int j = lane; j < Nc; j += 32) {
        float v = __fadd_rn(__fmul_rn(__fmul_rn(__fsub_rn(row[j], m), r), gg), bb);
        v = (v >= 0.f) ? v : SLOPEc * v;
        mx = fmaxf(mx, v);
        sm += v;
    }
    for (int off = 16; off; off >>= 1) {
        mx = fmaxf(mx, __shfl_xor_sync(0xffffffffu, mx, off));
        sm += __shfl_xor_sync(0xffffffffu, sm, off);
    }
    if (lane == 0) {
        p[b * 2 * EMBc + o] = mx;
        p[b * 2 * EMBc + EMBc + o] = sm * (1.0f / Nc);
    }
}

// fully-connected + batch BN (over B=8, fp64 moments over 8 values) + lrelu
__global__ void fc_bn_kernel(const float* __restrict__ in, const float* __restrict__ W,
                             const float* __restrict__ bias, const float* __restrict__ g,
                             const float* __restrict__ bta, float* __restrict__ out,
                             int Cin, int Cout)
{
    int j = blockIdx.x, t = threadIdx.x;
    float a[Bc];
#pragma unroll
    for (int b_ = 0; b_ < Bc; b_++) a[b_] = 0.f;
    for (int e = t; e < Cin; e += 64) {
        float w = W[(size_t)j * Cin + e];
#pragma unroll
        for (int b_ = 0; b_ < Bc; b_++) a[b_] = fmaf(w, in[b_ * Cin + e], a[b_]);
    }
    __shared__ float red[64][Bc];
#pragma unroll
    for (int b_ = 0; b_ < Bc; b_++) red[t][b_] = a[b_];
    __syncthreads();
    for (int s = 32; s > 0; s >>= 1) {
        if (t < s) {
#pragma unroll
            for (int b_ = 0; b_ < Bc; b_++) red[t][b_] += red[t + s][b_];
        }
        __syncthreads();
    }
    if (t < Bc) {
        float bb = bias ? bias[j] : 0.f;
        float vals[Bc];
        double mean = 0.0;
#pragma unroll
        for (int b_ = 0; b_ < Bc; b_++) { vals[b_] = red[0][b_] + bb; mean += (double)vals[b_]; }
        mean *= (1.0 / Bc);
        double var = 0.0;
#pragma unroll
        for (int b_ = 0; b_ < Bc; b_++) { double d = (double)vals[b_] - mean; var += d * d; }
        var *= (1.0 / Bc);
        float m = (float)mean;
        float r = (float)rsqrt(var + EPSc);
        float y = __fadd_rn(__fmul_rn(__fmul_rn(__fsub_rn(vals[t], m), r), g[j]), bta[j]);
        out[t * Cout + j] = (y >= 0.f) ? y : SLOPEc * y;
    }
}

__global__ void fc3_kernel(const float* __restrict__ in, const float* __restrict__ W,
                           const float* __restrict__ bias, float* __restrict__ out)
{
    int t = threadIdx.x;
    if (t >= Bc * 40) return;
    int b = t / 40, j = t % 40;
    float s = 0.f;
    for (int e = 0; e < 256; e++) s = fmaf(W[j * 256 + e], in[b * 256 + e], s);
    out[t] = __fadd_rn(s, bias[j]);
}

// ---------------- host orchestration ----------------

static void run_edge_block(const float* xin, int C, int O,
                           const float* wTseg, const float* g, const float* bta,
                           float* xout,
                           float2* dist, float2* xxp, int* idxp,
                           float* ymax, double* statseg)
{
    xx_kernel<<<(Bc * Nc + 255) / 256, 256>>>(xin, xxp, C);
    dist_kernel<<<dim3(Nc / 64, Nc / 64, Bc), 256>>>(xin, xxp, dist, C);
    topk_kernel<<<Bc * Nc, 256>>>(dist, idxp);
    size_t shm = (size_t)(2 * C * Kc + C) * sizeof(float) + Kc * sizeof(int);
    edgeconv_kernel<<<dim3(Nc, Bc), O, shm>>>(xin, wTseg, idxp, ymax, statseg, C, O);
    bnapply_kernel<<<dim3(Nc / 32, O / 32, Bc), dim3(32, 8)>>>(ymax, statseg, g, bta, xout, O,
                                                               1.0 / (double)(Bc * Nc * Kc));
}

extern "C" void kernel_launch(void* const* d_in, const int* in_sizes, int n_in,
                              void* d_out, int out_size)
{
    const float* x   = (const float*)d_in[0];
    const float* w1  = (const float*)d_in[1];
    const float* w2  = (const float*)d_in[2];
    const float* w3  = (const float*)d_in[3];
    const float* w4  = (const float*)d_in[4];
    const float* w5  = (const float*)d_in[5];
    const float* lw1 = (const float*)d_in[6];
    const float* lw2 = (const float*)d_in[7];
    const float* lb2 = (const float*)d_in[8];
    const float* lw3 = (const float*)d_in[9];
    const float* lb3 = (const float*)d_in[10];
    const float* g1 = (const float*)d_in[11]; const float* b1 = (const float*)d_in[12];
    const float* g2 = (const float*)d_in[13]; const float* b2 = (const float*)d_in[14];
    const float* g3 = (const float*)d_in[15]; const float* b3 = (const float*)d_in[16];
    const float* g4 = (const float*)d_in[17]; const float* b4 = (const float*)d_in[18];
    const float* g5 = (const float*)d_in[19]; const float* b5 = (const float*)d_in[20];
    const float* g6 = (const float*)d_in[21]; const float* b6 = (const float*)d_in[22];
    const float* g7 = (const float*)d_in[23]; const float* b7 = (const float*)d_in[24];

    float *wT, *ymax, *x1b, *x2b, *x3b, *x4b, *z5, *pbuf, *h1, *h2;
    float2 *dist, *xxp;
    double* stats;
    int* idxp;
    cudaGetSymbolAddress((void**)&dist,  g_dist2);
    cudaGetSymbolAddress((void**)&xxp,   g_xx2);
    cudaGetSymbolAddress((void**)&idxp,  g_idx);
    cudaGetSymbolAddress((void**)&wT,    g_wT);
    cudaGetSymbolAddress((void**)&ymax,  g_ymax);
    cudaGetSymbolAddress((void**)&stats, g_statsd);
    cudaGetSymbolAddress((void**)&x1b,   g_x1);
    cudaGetSymbolAddress((void**)&x2b,   g_x2);
    cudaGetSymbolAddress((void**)&x3b,   g_x3);
    cudaGetSymbolAddress((void**)&x4b,   g_x4);
    cudaGetSymbolAddress((void**)&z5,    g_z5);
    cudaGetSymbolAddress((void**)&pbuf,  g_p);
    cudaGetSymbolAddress((void**)&h1,    g_h1);
    cudaGetSymbolAddress((void**)&h2,    g_h2);

    transpose_all<<<(90496 + 255) / 256, 256>>>(w1, w2, w3, w4, wT);
    zerostats_kernel<<<12, 256>>>(stats);

    run_edge_block(x,   3,   64,  wT + WT_OFF1, g1, b1, x1b, dist, xxp, idxp, ymax, stats + ST_OFF1);
    run_edge_block(x1b, 64,  64,  wT + WT_OFF2, g2, b2, x2b, dist, xxp, idxp, ymax, stats + ST_OFF2);
    run_edge_block(x2b, 64,  128, wT + WT_OFF3, g3, b3, x3b, dist, xxp, idxp, ymax, stats + ST_OFF3);
    run_edge_block(x3b, 128, 256, wT + WT_OFF4, g4, b4, x4b, dist, xxp, idxp, ymax, stats + ST_OFF4);

    conv5_kernel<<<dim3(Nc / 64, EMBc / 64, Bc), 256>>>(w5, x1b, x2b, x3b, x4b, z5, stats + ST_OFF5);
    pool5_kernel<<<dim3(EMBc, Bc), 32>>>(z5, stats + ST_OFF5, g5, b5, pbuf);

    fc_bn_kernel<<<512, 64>>>(pbuf, lw1, nullptr, g6, b6, h1, 2 * EMBc, 512);
    fc_bn_kernel<<<256, 64>>>(h1, lw2, lb2, g7, b7, h2, 512, 256);
    fc3_kernel<<<1, 320>>>(h2, lw3, lb3, (float*)d_out);
}

// round 11
// speedup vs baseline: 1.9470x; 1.0333x over previous
#include <cuda_runtime.h>
#include <cstdint>
#include <math.h>

#define Bc 8
#define Nc 2048
#define Kc 20
#define EMBc 1024
#define EPSc 1e-5
#define SLOPEc 0.2f

typedef unsigned long long u64;

// ---------------- packed f32x2 helpers (exact dual IEEE fp32 ops) ----------------
__device__ __forceinline__ u64 pack2(float lo, float hi)
{
    u64 r; asm("mov.b64 %0, {%1, %2};" : "=l"(r) : "f"(lo), "f"(hi)); return r;
}
__device__ __forceinline__ void unpack2(u64 v, float& lo, float& hi)
{
    asm("mov.b64 {%0, %1}, %2;" : "=f"(lo), "=f"(hi) : "l"(v));
}
__device__ __forceinline__ u64 fma2(u64 a, u64 b, u64 c)
{
    u64 d; asm("fma.rn.f32x2 %0, %1, %2, %3;" : "=l"(d) : "l"(a), "l"(b), "l"(c)); return d;
}
__device__ __forceinline__ u64 add2(u64 a, u64 b)
{
    u64 d; asm("add.rn.f32x2 %0, %1, %2;" : "=l"(d) : "l"(a), "l"(b)); return d;
}
__device__ __forceinline__ u64 sub2(u64 a, u64 b)
{
    return fma2(b, 0xBF800000BF800000ull, a);
}

// ---------------- scratch ----------------
__device__ float2 g_dist2[(size_t)Bc * Nc * Nc];
__device__ float2 g_xx2[Bc * Nc];
__device__ int    g_idx[Bc * Nc * Kc];
__device__ float  g_x1[Bc * 64 * Nc];
__device__ float  g_x2[Bc * 64 * Nc];
__device__ float  g_x3[Bc * 128 * Nc];
__device__ float  g_x4[Bc * 256 * Nc];
__device__ float  g_wT[90496];
__device__ float  g_ymax[Bc * Nc * 256];
__device__ double g_statsd[3072];
__device__ float  g_z5[Bc * EMBc * Nc];
__device__ float  g_p[Bc * 2 * EMBc];
__device__ float  g_h1[Bc * 512];
__device__ float  g_h2[Bc * 256];

#define WT_OFF1 0
#define WT_OFF2 384
#define WT_OFF3 8576
#define WT_OFF4 24960
#define ST_OFF1 0
#define ST_OFF2 128
#define ST_OFF3 256
#define ST_OFF4 512
#define ST_OFF5 1024

// ---------------- double-float helpers ----------------
__device__ __forceinline__ void two_sum(float a, float b, float& s, float& e)
{
    s = __fadd_rn(a, b);
    float bp = __fsub_rn(s, a);
    e = __fadd_rn(__fsub_rn(a, __fsub_rn(s, bp)), __fsub_rn(b, bp));
}

__device__ __forceinline__ float2 dd_sub(float ah, float al, float2 b)
{
    float s1  = __fsub_rn(ah, b.x);
    float v   = __fsub_rn(s1, ah);
    float err = __fsub_rn(__fsub_rn(ah, __fsub_rn(s1, v)), __fadd_rn(b.x, v));
    err = __fadd_rn(err, __fsub_rn(al, b.y));
    float hi = __fadd_rn(s1, err);
    float lo = __fsub_rn(err, __fsub_rn(hi, s1));
    return make_float2(hi, lo);
}

// ---------------- kernels ----------------

// w1:(64,6) w2:(64,128) w3:(128,128) w4:(256,256)
__global__ void transpose_all(const float* __restrict__ w1, const float* __restrict__ w2,
                              const float* __restrict__ w3, const float* __restrict__ w4,
                              float* __restrict__ wT)
{
    int t = blockIdx.x * blockDim.x + threadIdx.x;
    const float* w; int O, C2, base, li;
    if (t < 384)        { w = w1; O = 64;  C2 = 6;   base = WT_OFF1; li = t; }
    else if (t < 8576)  { w = w2; O = 64;  C2 = 128; base = WT_OFF2; li = t - 384; }
    else if (t < 24960) { w = w3; O = 128; C2 = 128; base = WT_OFF3; li = t - 8576; }
    else if (t < 90496) { w = w4; O = 256; C2 = 256; base = WT_OFF4; li = t - 24960; }
    else return;
    int o = li / C2, c = li % C2;
    wT[base + c * O + o] = w[li];
}

__global__ void zerostats_kernel(double* __restrict__ stats)
{
    int t = blockIdx.x * blockDim.x + threadIdx.x;
    if (t < 3072) stats[t] = 0.0;
}

__global__ void xx_kernel(const float* __restrict__ x, float2* __restrict__ xx2, int C)
{
    int i = blockIdx.x * blockDim.x + threadIdx.x;
    if (i >= Bc * Nc) return;
    int b = i / Nc, n = i % Nc;
    double s = 0.0;
    for (int c = 0; c < C; c++) {
        double v = (double)x[((size_t)b * C + c) * Nc + n];
        s += v * v;
    }
    float hi = (float)s;
    float lo = (float)(s - (double)hi);
    xx2[i] = make_float2(hi, lo);
}

// pd = 2*dot - xx_n - xx_m as double-float (unchanged from R10 - bit-exact path)
__global__ void dist_kernel(const float* __restrict__ x, const float2* __restrict__ xx2,
                            float2* __restrict__ dist, int C)
{
    __shared__ float sn[8][64];
    __shared__ float sm_[8][64];
    int b = blockIdx.z;
    int n0 = blockIdx.y * 64, m0 = blockIdx.x * 64;
    int t = threadIdx.x;
    int tx = t & 15, ty = t >> 4;
    u64 s2[4][2], e2[4][2];
#pragma unroll
    for (int i = 0; i < 4; i++)
#pragma unroll
        for (int jp = 0; jp < 2; jp++) { s2[i][jp] = 0ull; e2[i][jp] = 0ull; }
    const float* xb = x + (size_t)b * C * Nc;

    for (int c0 = 0; c0 < C; c0 += 8) {
#pragma unroll
        for (int r = 0; r < 2; r++) {
            int ei = t + r * 256;
            int cc = ei >> 6, j = ei & 63;
            int c = c0 + cc;
            sn[cc][j]  = (c < C) ? xb[(size_t)c * Nc + n0 + j] : 0.f;
            sm_[cc][j] = (c < C) ? xb[(size_t)c * Nc + m0 + j] : 0.f;
        }
        __syncthreads();
        u64 f2[4][2];
#pragma unroll
        for (int i = 0; i < 4; i++) { f2[i][0] = 0ull; f2[i][1] = 0ull; }
#pragma unroll
        for (int q = 0; q < 8; q++) {
            float4 nv = *(const float4*)&sn[q][ty * 4];
            float4 mv = *(const float4*)&sm_[q][tx * 4];
            u64 m01 = pack2(mv.x, mv.y);
            u64 m23 = pack2(mv.z, mv.w);
            float nn[4] = {nv.x, nv.y, nv.z, nv.w};
#pragma unroll
            for (int i = 0; i < 4; i++) {
                u64 np = pack2(nn[i], nn[i]);
                f2[i][0] = fma2(np, m01, f2[i][0]);
                f2[i][1] = fma2(np, m23, f2[i][1]);
            }
        }
#pragma unroll
        for (int i = 0; i < 4; i++)
#pragma unroll
            for (int jp = 0; jp < 2; jp++) {
                u64 tt = add2(s2[i][jp], f2[i][jp]);
                u64 bp = sub2(tt, s2[i][jp]);
                u64 ea = sub2(s2[i][jp], sub2(tt, bp));
                u64 eb = sub2(f2[i][jp], bp);
                e2[i][jp] = add2(e2[i][jp], add2(ea, eb));
                s2[i][jp] = tt;
            }
        __syncthreads();
    }
    int n = n0 + ty * 4, m = m0 + tx * 4;
    float s[4][4], e[4][4];
#pragma unroll
    for (int i = 0; i < 4; i++) {
        unpack2(s2[i][0], s[i][0], s[i][1]);
        unpack2(s2[i][1], s[i][2], s[i][3]);
        unpack2(e2[i][0], e[i][0], e[i][1]);
        unpack2(e2[i][1], e[i][2], e[i][3]);
    }
    float2 xn[4], xm[4];
#pragma unroll
    for (int i = 0; i < 4; i++) { xn[i] = xx2[b * Nc + n + i]; xm[i] = xx2[b * Nc + m + i]; }
    float2* dr = dist + (size_t)b * Nc * Nc;
#pragma unroll
    for (int i = 0; i < 4; i++)
#pragma unroll
        for (int j = 0; j < 4; j++) {
            float dh, dl;
            two_sum(s[i][j], e[i][j], dh, dl);
            dh = __fmul_rn(dh, 2.f);
            dl = __fmul_rn(dl, 2.f);
            float2 r1 = dd_sub(dh, dl, xn[i]);
            float2 r2 = dd_sub(r1.x, r1.y, xm[j]);
            dr[(size_t)(n + i) * Nc + m + j] = r2;
        }
}

// merge-based top-20: per-thread Batcher sort of 8 keys, shuffle-only warp merge,
// then warp-0 merges the 8 per-warp lists. Total order: (val desc, idx asc).
#define CE(i, j) { \
    bool sw = (vx[j] > vx[i]) || (vx[j] == vx[i] && (vy[j] > vy[i] || (vy[j] == vy[i] && vi[j] < vi[i]))); \
    if (sw) { float tx_ = vx[i]; vx[i] = vx[j]; vx[j] = tx_; \
              float ty_ = vy[i]; vy[i] = vy[j]; vy[j] = ty_; \
              int   ti_ = vi[i]; vi[i] = vi[j]; vi[j] = ti_; } }

__global__ void topk_kernel(const float2* __restrict__ dist, int* __restrict__ idx)
{
    int row = blockIdx.x;
    int t = threadIdx.x;
    int lane = t & 31, wid = t >> 5;
    const float4* d4 = (const float4*)(dist + (size_t)row * Nc) + t * 4;
    float vx[8], vy[8];
    int vi[8];
#pragma unroll
    for (int q = 0; q < 4; q++) {
        float4 f = d4[q];
        vx[2 * q]     = f.x; vy[2 * q]     = f.y;
        vx[2 * q + 1] = f.z; vy[2 * q + 1] = f.w;
        vi[2 * q]     = t * 8 + 2 * q;
        vi[2 * q + 1] = t * 8 + 2 * q + 1;
    }
    // Batcher odd-even mergesort, 8 elements, descending by (val desc, idx asc)
    CE(0,1) CE(2,3) CE(4,5) CE(6,7)
    CE(0,2) CE(1,3) CE(4,6) CE(5,7)
    CE(1,2) CE(5,6)
    CE(0,4) CE(1,5) CE(2,6) CE(3,7)
    CE(2,4) CE(3,5)
    CE(1,2) CE(3,4) CE(5,6)

    __shared__ float swx[8][Kc], swy[8][Kc];
    __shared__ int   swi[8][Kc];

    for (int kk = 0; kk < Kc; kk++) {
        float bx = vx[0], by = vy[0];
        int bi = vi[0], bl = lane;
#pragma unroll
        for (int off = 16; off; off >>= 1) {
            float ox = __shfl_xor_sync(0xffffffffu, bx, off);
            float oy = __shfl_xor_sync(0xffffffffu, by, off);
            int   oi = __shfl_xor_sync(0xffffffffu, bi, off);
            int   ol = __shfl_xor_sync(0xffffffffu, bl, off);
            if (ox > bx || (ox == bx && (oy > by || (oy == by && oi < bi)))) {
                bx = ox; by = oy; bi = oi; bl = ol;
            }
        }
        if (lane == 0) { swx[wid][kk] = bx; swy[wid][kk] = by; swi[wid][kk] = bi; }
        if (lane == bl) {
#pragma unroll
            for (int q = 0; q < 7; q++) { vx[q] = vx[q + 1]; vy[q] = vy[q + 1]; vi[q] = vi[q + 1]; }
            vx[7] = -INFINITY; vy[7] = -INFINITY; vi[7] = 0x7FFFFFFF;
        }
    }
    __syncthreads();

    if (t < 32) {
        bool act = lane < 8;
        int pos = 0;
        float hx = act ? swx[lane][0] : -INFINITY;
        float hy = act ? swy[lane][0] : -INFINITY;
        int   hidx = act ? swi[lane][0] : 0x7FFFFFFF;
        int* out = idx + (size_t)row * Kc;
        for (int kk = 0; kk < Kc; kk++) {
            float bx = hx, by = hy;
            int bi = hidx, bl = lane;
#pragma unroll
            for (int off = 16; off; off >>= 1) {
                float ox = __shfl_xor_sync(0xffffffffu, bx, off);
                float oy = __shfl_xor_sync(0xffffffffu, by, off);
                int   oi = __shfl_xor_sync(0xffffffffu, bi, off);
                int   ol = __shfl_xor_sync(0xffffffffu, bl, off);
                if (ox > bx || (ox == bx && (oy > by || (oy == by && oi < bi)))) {
                    bx = ox; by = oy; bi = oi; bl = ol;
                }
            }
            if (lane == 0) out[kk] = bi;
            if (lane == bl) {
                pos++;
                if (pos < Kc) { hx = swx[lane][pos]; hy = swy[lane][pos]; hidx = swi[lane][pos]; }
                else          { hx = -INFINITY; hy = -INFINITY; hidx = 0x7FFFFFFF; }
            }
        }
    }
}

// fused edgeconv: G=2 n per block, LDS.128 feat loads, FFMA2 mainloop (bit-identical
// per-n chains), dd fp32 stat accumulation -> single fp64 atomic per channel pair.
__global__ void edgeconv_kernel(const float* __restrict__ xin, const float* __restrict__ wT,
                                const int* __restrict__ idx, float* __restrict__ ymax,
                                double* __restrict__ stats, int C, int O)
{
    extern __shared__ float shm[];
    int nA = blockIdx.x * 2, nB = nA + 1;
    int b = blockIdx.y, t = threadIdx.x;
    int C2 = 2 * C;
    float* featA = shm;
    float* featB = shm + C2 * Kc;
    float* ctrA  = featB + C2 * Kc;
    float* ctrB  = ctrA + C;
    int*   sidx  = (int*)(ctrB + C);   // [2*Kc]: A then B

    if (t < Kc)      sidx[t]      = idx[((size_t)b * Nc + nA) * Kc + t];
    else if (t < 2 * Kc) sidx[t]  = idx[((size_t)b * Nc + nB) * Kc + (t - Kc)];
    for (int c = t; c < C; c += blockDim.x) {
        ctrA[c] = xin[((size_t)b * C + c) * Nc + nA];
        ctrB[c] = xin[((size_t)b * C + c) * Nc + nB];
    }
    __syncthreads();
    for (int e = t; e < C * Kc; e += blockDim.x) {
        int c = e / Kc, k = e - c * Kc;
        float cvA = ctrA[c], cvB = ctrB[c];
        float nvA = xin[((size_t)b * C + c) * Nc + sidx[k]];
        float nvB = xin[((size_t)b * C + c) * Nc + sidx[Kc + k]];
        featA[c * Kc + k]       = __fsub_rn(nvA, cvA);
        featA[(C + c) * Kc + k] = cvA;
        featB[c * Kc + k]       = __fsub_rn(nvB, cvB);
        featB[(C + c) * Kc + k] = cvB;
    }
    __syncthreads();

    u64 accA[Kc / 2], accB[Kc / 2];
#pragma unroll
    for (int p = 0; p < Kc / 2; p++) { accA[p] = 0ull; accB[p] = 0ull; }

#pragma unroll 2
    for (int c2 = 0; c2 < C2; c2++) {
        float w = wT[c2 * O + t];
        u64 wp = pack2(w, w);
        const ulonglong2* fA = reinterpret_cast<const ulonglong2*>(featA + c2 * Kc);
        const ulonglong2* fB = reinterpret_cast<const ulonglong2*>(featB + c2 * Kc);
#pragma unroll
        for (int p = 0; p < 5; p++) {
            ulonglong2 fa = fA[p];
            accA[2 * p]     = fma2(fa.x, wp, accA[2 * p]);
            accA[2 * p + 1] = fma2(fa.y, wp, accA[2 * p + 1]);
        }
#pragma unroll
        for (int p = 0; p < 5; p++) {
            ulonglong2 fb = fB[p];
            accB[2 * p]     = fma2(fb.x, wp, accB[2 * p]);
            accB[2 * p + 1] = fma2(fb.y, wp, accB[2 * p + 1]);
        }
    }

    // epilogue per n: max + dd fp32 sum/sumsq (error ~1e-13, safely below ref noise)
    float acc[Kc];
    double Stot = 0.0, Qtot = 0.0;
#pragma unroll
    for (int half = 0; half < 2; half++) {
        u64* a2 = half ? accB : accA;
#pragma unroll
        for (int p = 0; p < Kc / 2; p++) unpack2(a2[p], acc[2 * p], acc[2 * p + 1]);
        float m = acc[0];
        float s = 0.f, se = 0.f, q = 0.f, qe = 0.f;
#pragma unroll
        for (int k = 0; k < Kc; k++) {
            float a = acc[k];
            m = fmaxf(m, a);
            float th, te;
            two_sum(s, a, th, te);
            s = th; se = __fadd_rn(se, te);
            float ph = __fmul_rn(a, a);
            float pl = fmaf(a, a, -ph);
            two_sum(q, ph, th, te);
            q = th; qe = __fadd_rn(qe, __fadd_rn(te, pl));
        }
        int n = half ? nB : nA;
        ymax[((size_t)b * Nc + n) * O + t] = m;
        Stot += (double)s + (double)se;
        Qtot += (double)q + (double)qe;
    }
    atomicAdd(&stats[t], Stot);
    atomicAdd(&stats[O + t], Qtot);
}

// BN + lrelu on max-pooled values, smem-tile transpose [b][n][o] -> [b][o][n]
__global__ void bnapply_kernel(const float* __restrict__ ymax, const double* __restrict__ stats,
                               const float* __restrict__ g, const float* __restrict__ bta,
                               float* __restrict__ xout, int O, double invcnt)
{
    __shared__ float tile[32][33];
    int b  = blockIdx.z;
    int o0 = blockIdx.y * 32;
    int n0 = blockIdx.x * 32;
    int tx = threadIdx.x, ty = threadIdx.y;
    int o = o0 + tx;
    double mean = stats[o] * invcnt;
    double var  = stats[O + o] * invcnt - mean * mean;
    float m = (float)mean;
    float r = (float)rsqrt(var + EPSc);
    float gg = g[o], bb = bta[o];
#pragma unroll
    for (int rr = 0; rr < 4; rr++) {
        int n = n0 + ty + rr * 8;
        float vv = ymax[((size_t)b * Nc + n) * O + o];
        float y = __fadd_rn(__fmul_rn(__fmul_rn(__fsub_rn(vv, m), r), gg), bb);
        tile[ty + rr * 8][tx] = (y >= 0.f) ? y : SLOPEc * y;
    }
    __syncthreads();
#pragma unroll
    for (int rr = 0; rr < 4; rr++) {
        int oo = o0 + ty + rr * 8;
        xout[((size_t)b * O + oo) * Nc + n0 + tx] = tile[tx][ty + rr * 8];
    }
}

// conv5 with FFMA2 mainloop; dd per-thread stats -> fp64 smem/global atomics
__global__ void conv5_kernel(const float* __restrict__ w5,
                             const float* __restrict__ x1, const float* __restrict__ x2,
                             const float* __restrict__ x3, const float* __restrict__ x4,
                             float* __restrict__ z, double* __restrict__ stats)
{
    __shared__ float As[16][68];
    __shared__ float Bs[16][64];
    __shared__ double rs[64], rss[64];
    int b  = blockIdx.z;
    int o0 = blockIdx.y * 64;
    int n0 = blockIdx.x * 64;
    int t = threadIdx.x;
    int tx = t & 15, ty = t >> 4;
    u64 acc2[4][2];
#pragma unroll
    for (int i = 0; i < 4; i++) { acc2[i][0] = 0ull; acc2[i][1] = 0ull; }

    for (int c0 = 0; c0 < 512; c0 += 16) {
#pragma unroll
        for (int r = 0; r < 4; r++) {
            int e = t + r * 256;
            int oo = e >> 4, cc = e & 15;
            As[cc][oo] = w5[(size_t)(o0 + oo) * 512 + c0 + cc];
            int cc2 = e >> 6, jj = e & 63;
            int ch = c0 + cc2;
            const float* src; int cl, Cb;
            if (ch < 64)       { src = x1; cl = ch;       Cb = 64;  }
            else if (ch < 128) { src = x2; cl = ch - 64;  Cb = 64;  }
            else if (ch < 256) { src = x3; cl = ch - 128; Cb = 128; }
            else               { src = x4; cl = ch - 256; Cb = 256; }
            Bs[cc2][jj] = src[((size_t)b * Cb + cl) * Nc + n0 + jj];
        }
        __syncthreads();
#pragma unroll
        for (int cc = 0; cc < 16; cc++) {
            float4 av4 = *(const float4*)&As[cc][ty * 4];
            float4 bv4 = *(const float4*)&Bs[cc][tx * 4];
            u64 b01 = pack2(bv4.x, bv4.y);
            u64 b23 = pack2(bv4.z, bv4.w);
            float av[4] = {av4.x, av4.y, av4.z, av4.w};
#pragma unroll
            for (int i = 0; i < 4; i++) {
                u64 ap = pack2(av[i], av[i]);
                acc2[i][0] = fma2(ap, b01, acc2[i][0]);
                acc2[i][1] = fma2(ap, b23, acc2[i][1]);
            }
        }
        __syncthreads();
    }
    float acc[4][4];
#pragma unroll
    for (int i = 0; i < 4; i++) {
        unpack2(acc2[i][0], acc[i][0], acc[i][1]);
        unpack2(acc2[i][1], acc[i][2], acc[i][3]);
    }
    if (t < 64) { rs[t] = 0.0; rss[t] = 0.0; }
    __syncthreads();
#pragma unroll
    for (int i = 0; i < 4; i++) {
        int o = o0 + ty * 4 + i;
        float s = 0.f, se = 0.f, q = 0.f, qe = 0.f;
#pragma unroll
        for (int j = 0; j < 4; j++) {
            float a = acc[i][j];
            float th, te;
            two_sum(s, a, th, te);
            s = th; se = __fadd_rn(se, te);
            float ph = __fmul_rn(a, a);
            float pl = fmaf(a, a, -ph);
            two_sum(q, ph, th, te);
            q = th; qe = __fadd_rn(qe, __fadd_rn(te, pl));
        }
        atomicAdd(&rs[ty * 4 + i],  (double)s + (double)se);
        atomicAdd(&rss[ty * 4 + i], (double)q + (double)qe);
        float4 v4 = make_float4(acc[i][0], acc[i][1], acc[i][2], acc[i][3]);
        *reinterpret_cast<float4*>(&z[((size_t)b * EMBc + o) * Nc + n0 + tx * 4]) = v4;
    }
    __syncthreads();
    if (t < 64) {
        atomicAdd(&stats[o0 + t], rs[t]);
        atomicAdd(&stats[EMBc + o0 + t], rss[t]);
    }
}

__global__ void pool5_kernel(const float* __restrict__ z, const double* __restrict__ stats,
                             const float* __restrict__ g, const float* __restrict__ bta,
                             float* __restrict__ p)
{
    int o = blockIdx.x, b = blockIdx.y, lane = threadIdx.x;
    const double inv = 1.0 / (double)(Bc * Nc);
    double mean = stats[o] * inv;
    double var  = stats[EMBc + o] * inv - mean * mean;
    float m = (float)mean;
    float r = (float)rsqrt(var + EPSc);
    float gg = g[o], bb = bta[o];
    const float* row = z + ((size_t)b * EMBc + o) * Nc;
    float mx = -INFINITY, sm = 0.f;
    for (int j = lane; j < Nc; j += 32) {
        float v = __fadd_rn(__fmul_rn(__fmul_rn(__fsub_rn(row[j], m), r), gg), bb);
        v = (v >= 0.f) ? v : SLOPEc * v;
        mx = fmaxf(mx, v);
        sm += v;
    }
    for (int off = 16; off; off >>= 1) {
        mx = fmaxf(mx, __shfl_xor_sync(0xffffffffu, mx, off));
        sm += __shfl_xor_sync(0xffffffffu, sm, off);
    }
    if (lane == 0) {
        p[b * 2 * EMBc + o] = mx;
        p[b * 2 * EMBc + EMBc + o] = sm * (1.0f / Nc);
    }
}

__global__ void fc_bn_kernel(const float* __restrict__ in, const float* __restrict__ W,
                             const float* __restrict__ bias, const float* __restrict__ g,
                             const float* __restrict__ bta, float* __restrict__ out,
                             int Cin, int Cout)
{
    int j = blockIdx.x, t = threadIdx.x;
    float a[Bc];
#pragma unroll
    for (int b_ = 0; b_ < Bc; b_++) a[b_] = 0.f;
    for (int e = t; e < Cin; e += 64) {
        float w = W[(size_t)j * Cin + e];
#pragma unroll
        for (int b_ = 0; b_ < Bc; b_++) a[b_] = fmaf(w, in[b_ * Cin + e], a[b_]);
    }
    __shared__ float red[64][Bc];
#pragma unroll
    for (int b_ = 0; b_ < Bc; b_++) red[t][b_] = a[b_];
    __syncthreads();
    for (int s = 32; s > 0; s >>= 1) {
        if (t < s) {
#pragma unroll
            for (int b_ = 0; b_ < Bc; b_++) red[t][b_] += red[t + s][b_];
        }
        __syncthreads();
    }
    if (t < Bc) {
        float bb = bias ? bias[j] : 0.f;
        float vals[Bc];
        double mean = 0.0;
#pragma unroll
        for (int b_ = 0; b_ < Bc; b_++) { vals[b_] = red[0][b_] + bb; mean += (double)vals[b_]; }
        mean *= (1.0 / Bc);
        double var = 0.0;
#pragma unroll
        for (int b_ = 0; b_ < Bc; b_++) { double d = (double)vals[b_] - mean; var += d * d; }
        var *= (1.0 / Bc);
        float m = (float)mean;
        float r = (float)rsqrt(var + EPSc);
        float y = __fadd_rn(__fmul_rn(__fmul_rn(__fsub_rn(vals[t], m), r), g[j]), bta[j]);
        out[t * Cout + j] = (y >= 0.f) ? y : SLOPEc * y;
    }
}

__global__ void fc3_kernel(const float* __restrict__ in, const float* __restrict__ W,
                           const float* __restrict__ bias, float* __restrict__ out)
{
    int t = threadIdx.x;
    if (t >= Bc * 40) return;
    int b = t / 40, j = t % 40;
    float s = 0.f;
    for (int e = 0; e < 256; e++) s = fmaf(W[j * 256 + e], in[b * 256 + e], s);
    out[t] = __fadd_rn(s, bias[j]);
}

// ---------------- host orchestration ----------------

static void run_edge_block(const float* xin, int C, int O,
                           const float* wTseg, const float* g, const float* bta,
                           float* xout,
                           float2* dist, float2* xxp, int* idxp,
                           float* ymax, double* statseg)
{
    xx_kernel<<<(Bc * Nc + 255) / 256, 256>>>(xin, xxp, C);
    dist_kernel<<<dim3(Nc / 64, Nc / 64, Bc), 256>>>(xin, xxp, dist, C);
    topk_kernel<<<Bc * Nc, 256>>>(dist, idxp);
    size_t shm = (size_t)(2 * (2 * C * Kc + C)) * sizeof(float) + 2 * Kc * sizeof(int);
    edgeconv_kernel<<<dim3(Nc / 2, Bc), O, shm>>>(xin, wTseg, idxp, ymax, statseg, C, O);
    bnapply_kernel<<<dim3(Nc / 32, O / 32, Bc), dim3(32, 8)>>>(ymax, statseg, g, bta, xout, O,
                                                               1.0 / (double)(Bc * Nc * Kc));
}

extern "C" void kernel_launch(void* const* d_in, const int* in_sizes, int n_in,
                              void* d_out, int out_size)
{
    const float* x   = (const float*)d_in[0];
    const float* w1  = (const float*)d_in[1];
    const float* w2  = (const float*)d_in[2];
    const float* w3  = (const float*)d_in[3];
    const float* w4  = (const float*)d_in[4];
    const float* w5  = (const float*)d_in[5];
    const float* lw1 = (const float*)d_in[6];
    const float* lw2 = (const float*)d_in[7];
    const float* lb2 = (const float*)d_in[8];
    const float* lw3 = (const float*)d_in[9];
    const float* lb3 = (const float*)d_in[10];
    const float* g1 = (const float*)d_in[11]; const float* b1 = (const float*)d_in[12];
    const float* g2 = (const float*)d_in[13]; const float* b2 = (const float*)d_in[14];
    const float* g3 = (const float*)d_in[15]; const float* b3 = (const float*)d_in[16];
    const float* g4 = (const float*)d_in[17]; const float* b4 = (const float*)d_in[18];
    const float* g5 = (const float*)d_in[19]; const float* b5 = (const float*)d_in[20];
    const float* g6 = (const float*)d_in[21]; const float* b6 = (const float*)d_in[22];
    const float* g7 = (const float*)d_in[23]; const float* b7 = (const float*)d_in[24];

    float *wT, *ymax, *x1b, *x2b, *x3b, *x4b, *z5, *pbuf, *h1, *h2;
    float2 *dist, *xxp;
    double* stats;
    int* idxp;
    cudaGetSymbolAddress((void**)&dist,  g_dist2);
    cudaGetSymbolAddress((void**)&xxp,   g_xx2);
    cudaGetSymbolAddress((void**)&idxp,  g_idx);
    cudaGetSymbolAddress((void**)&wT,    g_wT);
    cudaGetSymbolAddress((void**)&ymax,  g_ymax);
    cudaGetSymbolAddress((void**)&stats, g_statsd);
    cudaGetSymbolAddress((void**)&x1b,   g_x1);
    cudaGetSymbolAddress((void**)&x2b,   g_x2);
    cudaGetSymbolAddress((void**)&x3b,   g_x3);
    cudaGetSymbolAddress((void**)&x4b,   g_x4);
    cudaGetSymbolAddress((void**)&z5,    g_z5);
    cudaGetSymbolAddress((void**)&pbuf,  g_p);
    cudaGetSymbolAddress((void**)&h1,    g_h1);
    cudaGetSymbolAddress((void**)&h2,    g_h2);

    transpose_all<<<(90496 + 255) / 256, 256>>>(w1, w2, w3, w4, wT);
    zerostats_kernel<<<12, 256>>>(stats);

    run_edge_block(x,   3,   64,  wT + WT_OFF1, g1, b1, x1b, dist, xxp, idxp, ymax, stats + ST_OFF1);
    run_edge_block(x1b, 64,  64,  wT + WT_OFF2, g2, b2, x2b, dist, xxp, idxp, ymax, stats + ST_OFF2);
    run_edge_block(x2b, 64,  128, wT + WT_OFF3, g3, b3, x3b, dist, xxp, idxp, ymax, stats + ST_OFF3);
    run_edge_block(x3b, 128, 256, wT + WT_OFF4, g4, b4, x4b, dist, xxp, idxp, ymax, stats + ST_OFF4);

    conv5_kernel<<<dim3(Nc / 64, EMBc / 64, Bc), 256>>>(w5, x1b, x2b, x3b, x4b, z5, stats + ST_OFF5);
    pool5_kernel<<<dim3(EMBc, Bc), 32>>>(z5, stats + ST_OFF5, g5, b5, pbuf);

    fc_bn_kernel<<<512, 64>>>(pbuf, lw1, nullptr, g6, b6, h1, 2 * EMBc, 512);
    fc_bn_kernel<<<256, 64>>>(h1, lw2, lb2, g7, b7, h2, 512, 256);
    fc3_kernel<<<1, 320>>>(h2, lw3, lb3, (float*)d_out);
}